// round 12
// baseline (speedup 1.0000x reference)
#include <cuda_runtime.h>
#include <cuda_bf16.h>
#include <math.h>
#include <cstdint>

#define NB 2
#define NT 2048
#define NH 16
#define HD 64
#define NC 1024
#define MTOT (NB*NT)   // 4096
#define NCHUNK 16      // T / 128

typedef __nv_bfloat16  bf16;
typedef __nv_bfloat162 bf162;

// ---------------------------------------------------------------------------
// Scratch (allocation-free rule: __device__ globals)
// ---------------------------------------------------------------------------
__device__ __align__(16) bf16 g_Xh[MTOT*NC],  g_Xl[MTOT*NC];
__device__ __align__(16) bf16 g_Wh[4*NC*NC],  g_Wl[4*NC*NC];
__device__ __align__(16) bf16 g_Qh[NB*NH*NT*HD], g_Ql[NB*NH*NT*HD];
__device__ __align__(16) bf16 g_Kh[NB*NH*NT*HD], g_Kl[NB*NH*NT*HD];
__device__ __align__(16) bf16 g_Vh[NB*NH*NT*HD], g_Vl[NB*NH*NT*HD];
__device__ __align__(16) float g_O[NB*NH*NT*HD];
__device__ __align__(16) bf16 g_Ynh[MTOT*NC], g_Ynl[MTOT*NC];
__device__ __align__(16) float g_U[NB*NH*NCHUNK*HD*HD];   // chunk summaries (fp32)
__device__ double2 g_gnp[NB*NH*NCHUNK];   // per-(bh,chunk) partial sums

// ---------------------------------------------------------------------------
// Helpers
// ---------------------------------------------------------------------------
__device__ __forceinline__ uint32_t smaddr(const void* p) {
    uint32_t a;
    asm("{ .reg .u64 t; cvta.to.shared.u64 t, %1; cvt.u32.u64 %0, t; }"
        : "=r"(a) : "l"(p));
    return a;
}
__device__ __forceinline__ void ldsm4(uint32_t r[4], uint32_t a) {
    asm volatile("ldmatrix.sync.aligned.m8n8.x4.shared.b16 {%0,%1,%2,%3}, [%4];"
        : "=r"(r[0]), "=r"(r[1]), "=r"(r[2]), "=r"(r[3]) : "r"(a));
}
__device__ __forceinline__ void ldsm4t(uint32_t r[4], uint32_t a) {
    asm volatile("ldmatrix.sync.aligned.m8n8.x4.trans.shared.b16 {%0,%1,%2,%3}, [%4];"
        : "=r"(r[0]), "=r"(r[1]), "=r"(r[2]), "=r"(r[3]) : "r"(a));
}
__device__ __forceinline__ void mma_bf(float c[4], const uint32_t a[4], const uint32_t b[2]) {
    asm volatile(
        "mma.sync.aligned.m16n8k16.row.col.f32.bf16.bf16.f32 "
        "{%0,%1,%2,%3}, {%4,%5,%6,%7}, {%8,%9}, {%0,%1,%2,%3};"
        : "+f"(c[0]), "+f"(c[1]), "+f"(c[2]), "+f"(c[3])
        : "r"(a[0]), "r"(a[1]), "r"(a[2]), "r"(a[3]), "r"(b[0]), "r"(b[1]));
}
__device__ __forceinline__ uint32_t pk2(float a, float b) {
    bf162 t = __floats2bfloat162_rn(a, b);
    return *reinterpret_cast<uint32_t*>(&t);
}
__device__ __forceinline__ float lg2gamma(int h) {
    double gamma = 1.0 - exp2(-5.0 - 0.5 * (double)h);
    return (float)log2(gamma);
}
__device__ __forceinline__ void cpa16(uint32_t s, const void* g) {
    asm volatile("cp.async.cg.shared.global [%0], [%1], 16;" :: "r"(s), "l"(g));
}
#define CP_COMMIT() asm volatile("cp.async.commit_group;" ::: "memory")
#define CP_WAIT0()  asm volatile("cp.async.wait_group 0;" ::: "memory")

__device__ __forceinline__ void split4(float4 v, uint2& hi, uint2& lo) {
    bf162 h0 = __floats2bfloat162_rn(v.x, v.y);
    bf162 h1 = __floats2bfloat162_rn(v.z, v.w);
    bf162 l0 = __floats2bfloat162_rn(v.x - __bfloat162float(h0.x),
                                     v.y - __bfloat162float(h0.y));
    bf162 l1 = __floats2bfloat162_rn(v.z - __bfloat162float(h1.x),
                                     v.w - __bfloat162float(h1.y));
    hi.x = *(uint32_t*)&h0; hi.y = *(uint32_t*)&h1;
    lo.x = *(uint32_t*)&l0; lo.y = *(uint32_t*)&l1;
}

// ---------------------------------------------------------------------------
// Fused split
// ---------------------------------------------------------------------------
#define NX4 (MTOT*NC/4)
#define NW4 (NC*NC/4)

__global__ __launch_bounds__(256) void split_all_kernel(
    const float4* __restrict__ x,  const float4* __restrict__ wq,
    const float4* __restrict__ wk, const float4* __restrict__ wv,
    const float4* __restrict__ wo)
{
    int i = blockIdx.x * 256 + threadIdx.x;
    uint2 hi, lo;
    if (i < NX4) {
        split4(x[i], hi, lo);
        *(uint2*)(g_Xh + 4 * (size_t)i) = hi;
        *(uint2*)(g_Xl + 4 * (size_t)i) = lo;
    } else {
        int j = i - NX4;
        int widx = j >> 18;
        int e = j & (NW4 - 1);
        const float4* w = (widx == 0) ? wq : (widx == 1) ? wk : (widx == 2) ? wv : wo;
        split4(w[e], hi, lo);
        *(uint2*)(g_Wh + (size_t)widx * NC * NC + 4 * (size_t)e) = hi;
        *(uint2*)(g_Wl + (size_t)widx * NC * NC + 4 * (size_t)e) = lo;
    }
}

// ---------------------------------------------------------------------------
// bf16x3 GEMM (R7/R10 config): BM=128, BN=128, warp tile 32x64, 2 CTAs/SM.
// ---------------------------------------------------------------------------
#define AST 40
#define KCH 32
#define SOA(buf,p) ((buf)*20480 + (p)*10240)
#define SOB(buf,p) (40960 + (buf)*20480 + (p)*10240)
#define GEMM_SMEM 81920

template<int MODE>
__global__ __launch_bounds__(256, 2) void gemm_mma(float* __restrict__ Cf) {
    extern __shared__ __align__(16) char sm[];
    const int tid = threadIdx.x, l = tid & 31, wid = tid >> 5;
    const int wm = wid & 3, wn = wid >> 2;
    const int r0 = blockIdx.x * 128, n0 = blockIdx.y * 128;
    const int z = blockIdx.z;
    const int wsel = (MODE == 0) ? z : 3;

    const bf16* Ah = (MODE == 0) ? g_Xh : g_Ynh;
    const bf16* Al = (MODE == 0) ? g_Xl : g_Ynl;
    const bf16* Wh = g_Wh + (size_t)wsel * NC * NC;
    const bf16* Wl = g_Wl + (size_t)wsel * NC * NC;
    const uint32_t sb = smaddr(sm);

    float acc[2][8][4];
#pragma unroll
    for (int mi = 0; mi < 2; mi++)
#pragma unroll
        for (int ni = 0; ni < 8; ni++)
#pragma unroll
            for (int q = 0; q < 4; q++) acc[mi][ni][q] = 0.f;

    auto load_chunk = [&](int kb, int buf) {
#pragma unroll
        for (int i = 0; i < 8; i++) {
            int j = tid + 256 * i;
            int row = (j >> 2) & 127, seg = j & 3, part = (j >> 9) & 1;
            if (j < 1024) {
                const bf16* src = (part ? Al : Ah) + (size_t)(r0 + row) * NC + kb + seg * 8;
                cpa16(sb + SOA(buf, part) + (row * AST + seg * 8) * 2, src);
            } else {
                const bf16* src = (part ? Wl : Wh) + (size_t)(n0 + row) * NC + kb + seg * 8;
                cpa16(sb + SOB(buf, part) + (row * AST + seg * 8) * 2, src);
            }
        }
    };

    load_chunk(0, 0);
    CP_COMMIT();

    for (int c = 0; c < KCH; c++) {
        const int buf = c & 1;
        CP_WAIT0();
        __syncthreads();
        if (c + 1 < KCH) {
            load_chunk((c + 1) * 32, buf ^ 1);
            CP_COMMIT();
        }
#pragma unroll
        for (int ks = 0; ks < 32; ks += 16) {
            uint32_t af[2][2][4];
#pragma unroll
            for (int p = 0; p < 2; p++)
#pragma unroll
                for (int mi = 0; mi < 2; mi++) {
                    int row = wm * 32 + mi * 16 + (l & 7) + ((l >> 3) & 1) * 8;
                    int col = ks + (l >> 4) * 8;
                    ldsm4(af[p][mi], sb + SOA(buf, p) + (row * AST + col) * 2);
                }
            {
                uint32_t b0[8][2];
#pragma unroll
                for (int na = 0; na < 4; na++) {
                    int row = wn * 64 + na * 16 + (l >> 4) * 8 + (l & 7);
                    int col = ks + ((l >> 3) & 1) * 8;
                    uint32_t r4[4];
                    ldsm4(r4, sb + SOB(buf, 0) + (row * AST + col) * 2);
                    b0[na * 2][0] = r4[0]; b0[na * 2][1] = r4[1];
                    b0[na * 2 + 1][0] = r4[2]; b0[na * 2 + 1][1] = r4[3];
                }
#pragma unroll
                for (int mi = 0; mi < 2; mi++)
#pragma unroll
                    for (int ni = 0; ni < 8; ni++) mma_bf(acc[mi][ni], af[0][mi], b0[ni]);
#pragma unroll
                for (int mi = 0; mi < 2; mi++)
#pragma unroll
                    for (int ni = 0; ni < 8; ni++) mma_bf(acc[mi][ni], af[1][mi], b0[ni]);
            }
            {
                uint32_t b1[8][2];
#pragma unroll
                for (int na = 0; na < 4; na++) {
                    int row = wn * 64 + na * 16 + (l >> 4) * 8 + (l & 7);
                    int col = ks + ((l >> 3) & 1) * 8;
                    uint32_t r4[4];
                    ldsm4(r4, sb + SOB(buf, 1) + (row * AST + col) * 2);
                    b1[na * 2][0] = r4[0]; b1[na * 2][1] = r4[1];
                    b1[na * 2 + 1][0] = r4[2]; b1[na * 2 + 1][1] = r4[3];
                }
#pragma unroll
                for (int mi = 0; mi < 2; mi++)
#pragma unroll
                    for (int ni = 0; ni < 8; ni++) mma_bf(acc[mi][ni], af[0][mi], b1[ni]);
            }
        }
    }

    const int g = l >> 2, tq = l & 3;
    bf16* oh = nullptr; bf16* ol = nullptr;
    if (MODE == 0) {
        oh = (z == 0) ? g_Qh : (z == 1) ? g_Kh : g_Vh;
        ol = (z == 0) ? g_Ql : (z == 1) ? g_Kl : g_Vl;
    }
#pragma unroll
    for (int mi = 0; mi < 2; mi++)
#pragma unroll
        for (int ni = 0; ni < 8; ni++) {
            int rbase = r0 + wm * 32 + mi * 16 + g;
            int n = n0 + wn * 64 + ni * 8 + 2 * tq;
#pragma unroll
            for (int rr = 0; rr < 2; rr++) {
                int row = rbase + rr * 8;
                float v0 = acc[mi][ni][rr * 2 + 0];
                float v1 = acc[mi][ni][rr * 2 + 1];
                if (MODE == 0) {
                    int b = row >> 11, t = row & (NT - 1);
                    int hh = n >> 6, d = n & 63;
                    size_t idx = (((size_t)b * NH + hh) * NT + t) * HD + d;
                    bf16 h0 = __float2bfloat16(v0);
                    bf16 h1 = __float2bfloat16(v1);
                    bf162 hv; hv.x = h0; hv.y = h1;
                    bf162 lv;
                    lv.x = __float2bfloat16(v0 - __bfloat162float(h0));
                    lv.y = __float2bfloat16(v1 - __bfloat162float(h1));
                    *(bf162*)(oh + idx) = hv;
                    *(bf162*)(ol + idx) = lv;
                } else {
                    *(float2*)(Cf + (size_t)row * NC + n) = make_float2(v0, v1);
                }
            }
        }
}

// ---------------------------------------------------------------------------
// Phase A: per-chunk KV summary -> fp32 U
// ---------------------------------------------------------------------------
#define CST 72
#define CWK(p) ((p)*18432)
#define CV(p)  (36864 + (p)*18432)
#define CHUNK_SMEM 73728

__global__ __launch_bounds__(128) void chunk_state_kernel() {
    extern __shared__ __align__(16) char sm[];
    const int tid = threadIdx.x, l = tid & 31, wid = tid >> 5;
    const int ci = blockIdx.x, bh = blockIdx.y, h = bh & (NH - 1);
    const float lg = lg2gamma(h);
    const uint32_t sb = smaddr(sm);
    const size_t base = (size_t)bh * NT * HD + (size_t)ci * 128 * HD;

    {
        const int j = tid;
        const float w = exp2f(lg * (float)(127 - j));
        const bf16* Kh = g_Kh + base + (size_t)j * HD;
        const bf16* Kl = g_Kl + base + (size_t)j * HD;
        const bf16* Vh = g_Vh + base + (size_t)j * HD;
        const bf16* Vl = g_Vl + base + (size_t)j * HD;
#pragma unroll
        for (int seg = 0; seg < 8; seg++) {
            uint4 khv = *(const uint4*)(Kh + seg * 8);
            uint4 klv = *(const uint4*)(Kl + seg * 8);
            const bf162* kh2 = (const bf162*)&khv;
            const bf162* kl2 = (const bf162*)&klv;
            uint32_t oh[4], ol[4];
#pragma unroll
            for (int q = 0; q < 4; q++) {
                float f0 = __bfloat162float(kh2[q].x) + __bfloat162float(kl2[q].x);
                float f1 = __bfloat162float(kh2[q].y) + __bfloat162float(kl2[q].y);
                f0 *= w; f1 *= w;
                bf16 h0 = __float2bfloat16(f0), h1 = __float2bfloat16(f1);
                float r0 = f0 - __bfloat162float(h0);
                float r1 = f1 - __bfloat162float(h1);
                ol[q] = pk2(r0, r1);
                bf162 hv; hv.x = h0; hv.y = h1;
                oh[q] = *(uint32_t*)&hv;
            }
            *(uint4*)(sm + CWK(0) + (j * CST + seg * 8) * 2) = *(uint4*)oh;
            *(uint4*)(sm + CWK(1) + (j * CST + seg * 8) * 2) = *(uint4*)ol;
            *(uint4*)(sm + CV(0) + (j * CST + seg * 8) * 2) = *(const uint4*)(Vh + seg * 8);
            *(uint4*)(sm + CV(1) + (j * CST + seg * 8) * 2) = *(const uint4*)(Vl + seg * 8);
        }
    }
    __syncthreads();

    float acc[8][4];
#pragma unroll
    for (int ni = 0; ni < 8; ni++)
#pragma unroll
        for (int q = 0; q < 4; q++) acc[ni][q] = 0.f;

#pragma unroll
    for (int ks = 0; ks < 8; ks++) {
        uint32_t ah[4], al[4];
        {
            int row = ks * 16 + (l & 7) + ((l >> 4) & 1) * 8;
            int col = 16 * wid + ((l >> 3) & 1) * 8;
            ldsm4t(ah, sb + CWK(0) + (row * CST + col) * 2);
            ldsm4t(al, sb + CWK(1) + (row * CST + col) * 2);
        }
        uint32_t bv[2][8][2];
#pragma unroll
        for (int p = 0; p < 2; p++)
#pragma unroll
            for (int na = 0; na < 4; na++) {
                int row = ks * 16 + ((l >> 3) & 1) * 8 + (l & 7);
                int col = na * 16 + (l >> 4) * 8;
                uint32_t r4[4];
                ldsm4t(r4, sb + CV(p) + (row * CST + col) * 2);
                bv[p][na * 2][0] = r4[0]; bv[p][na * 2][1] = r4[1];
                bv[p][na * 2 + 1][0] = r4[2]; bv[p][na * 2 + 1][1] = r4[3];
            }
#pragma unroll
        for (int ni = 0; ni < 8; ni++) mma_bf(acc[ni], ah, bv[0][ni]);
#pragma unroll
        for (int ni = 0; ni < 8; ni++) mma_bf(acc[ni], ah, bv[1][ni]);
#pragma unroll
        for (int ni = 0; ni < 8; ni++) mma_bf(acc[ni], al, bv[0][ni]);
    }

    float* U = g_U + ((size_t)bh * NCHUNK + ci) * HD * HD;
    const int g = l >> 2, tq = l & 3;
#pragma unroll
    for (int ni = 0; ni < 8; ni++) {
        int col = ni * 8 + 2 * tq;
        int row1 = 16 * wid + g, row2 = row1 + 8;
        *(float2*)(U + row1 * HD + col) = make_float2(acc[ni][0], acc[ni][1]);
        *(float2*)(U + row2 * HD + col) = make_float2(acc[ni][2], acc[ni][3]);
    }
}

// ---------------------------------------------------------------------------
// Phase C: intra-chunk quadratic + fused fp32-U state scan + GN partial.
// ---------------------------------------------------------------------------
#define RST 72
#define RQ(p)  ((p)*18432)
#define RK(p)  (36864 + (p)*9216)
#define RV(p)  (55296 + (p)*9216)
#define RDW    73728
#define RET_SMEM 74752

__global__ __launch_bounds__(256, 2) void retention_chunk_kernel() {
    extern __shared__ __align__(16) char sm[];
    float* dw = (float*)(sm + RDW);
    const int tid = threadIdx.x, l = tid & 31, wid = tid >> 5;
    const int bh = blockIdx.y, h = bh & (NH - 1);
    const int ci = blockIdx.x;
    const int t0 = ci * 128;
    const float lg = lg2gamma(h);
    const uint32_t sb = smaddr(sm);
    const size_t base = (size_t)bh * NT * HD;

#pragma unroll
    for (int p = 0; p < 2; p++) {
        const bf16* Qp = (p ? g_Ql : g_Qh) + base + (size_t)t0 * HD;
#pragma unroll
        for (int i = 0; i < 4; i++) {
            int flat = tid + 256 * i;
            int row = flat >> 3, seg = flat & 7;
            uint4 v = *(const uint4*)(Qp + (size_t)row * HD + seg * 8);
            *(uint4*)(sm + RQ(p) + (row * RST + seg * 8) * 2) = v;
        }
    }
    __syncthreads();

    const uint32_t aq_addr_base = sb + ((wid * 16 + (l & 7) + ((l >> 3) & 1) * 8) * RST
                                        + (l >> 4) * 8) * 2;

    float oacc[8][4];
#pragma unroll
    for (int ni = 0; ni < 8; ni++)
#pragma unroll
        for (int q = 0; q < 4; q++) oacc[ni][q] = 0.f;

    const int g = l >> 2, tq = l & 3;
    const int il = 16 * wid + g;

    for (int s0 = t0; s0 <= t0 + 64; s0 += 64) {
        __syncthreads();
#pragma unroll
        for (int p = 0; p < 2; p++) {
            const bf16* Kp = (p ? g_Kl : g_Kh) + base + (size_t)s0 * HD;
            const bf16* Vp = (p ? g_Vl : g_Vh) + base + (size_t)s0 * HD;
#pragma unroll
            for (int i = 0; i < 2; i++) {
                int flat = tid + 256 * i;
                int row = flat >> 3, seg = flat & 7;
                uint4 kv = *(const uint4*)(Kp + (size_t)row * HD + seg * 8);
                *(uint4*)(sm + RK(p) + (row * RST + seg * 8) * 2) = kv;
                uint4 vv = *(const uint4*)(Vp + (size_t)row * HD + seg * 8);
                *(uint4*)(sm + RV(p) + (row * RST + seg * 8) * 2) = vv;
            }
        }
        if (tid < 192) {
            int diff = t0 - s0 - 63 + tid;
            dw[tid] = (diff >= 0) ? 0.125f * exp2f(lg * (float)diff) : 0.f;
        }
        __syncthreads();

        float sacc[8][4];
#pragma unroll
        for (int ni = 0; ni < 8; ni++)
#pragma unroll
            for (int q = 0; q < 4; q++) sacc[ni][q] = 0.f;
#pragma unroll
        for (int kc = 0; kc < 4; kc++) {
            uint32_t aq0[4], aq1[4];
            ldsm4(aq0, aq_addr_base + RQ(0) + kc * 32);
            ldsm4(aq1, aq_addr_base + RQ(1) + kc * 32);
            uint32_t bk[2][8][2];
#pragma unroll
            for (int p = 0; p < 2; p++)
#pragma unroll
                for (int na = 0; na < 4; na++) {
                    int row = na * 16 + (l >> 4) * 8 + (l & 7);
                    int col = kc * 16 + ((l >> 3) & 1) * 8;
                    uint32_t r4[4];
                    ldsm4(r4, sb + RK(p) + (row * RST + col) * 2);
                    bk[p][na * 2][0] = r4[0]; bk[p][na * 2][1] = r4[1];
                    bk[p][na * 2 + 1][0] = r4[2]; bk[p][na * 2 + 1][1] = r4[3];
                }
#pragma unroll
            for (int ni = 0; ni < 8; ni++) mma_bf(sacc[ni], aq0, bk[0][ni]);
#pragma unroll
            for (int ni = 0; ni < 8; ni++) mma_bf(sacc[ni], aq0, bk[1][ni]);
#pragma unroll
            for (int ni = 0; ni < 8; ni++) mma_bf(sacc[ni], aq1, bk[0][ni]);
        }

#pragma unroll
        for (int ni = 0; ni < 8; ni++) {
            int jb = ni * 8 + 2 * tq;
            sacc[ni][0] *= dw[63 + il - jb];
            sacc[ni][1] *= dw[63 + il - (jb + 1)];
            sacc[ni][2] *= dw[63 + il + 8 - jb];
            sacc[ni][3] *= dw[63 + il + 8 - (jb + 1)];
        }

        uint32_t ash[4][4], asl[4][4];
#pragma unroll
        for (int kc = 0; kc < 4; kc++) {
            const float* e0 = sacc[2 * kc];
            const float* e1 = sacc[2 * kc + 1];
            float src[8] = {e0[0], e0[1], e0[2], e0[3], e1[0], e1[1], e1[2], e1[3]};
            float hv[8], lv[8];
#pragma unroll
            for (int q = 0; q < 8; q++) {
                bf16 hb = __float2bfloat16(src[q]);
                hv[q] = __bfloat162float(hb);
                lv[q] = src[q] - hv[q];
            }
            ash[kc][0] = pk2(hv[0], hv[1]); ash[kc][1] = pk2(hv[2], hv[3]);
            ash[kc][2] = pk2(hv[4], hv[5]); ash[kc][3] = pk2(hv[6], hv[7]);
            asl[kc][0] = pk2(lv[0], lv[1]); asl[kc][1] = pk2(lv[2], lv[3]);
            asl[kc][2] = pk2(lv[4], lv[5]); asl[kc][3] = pk2(lv[6], lv[7]);
        }

#pragma unroll
        for (int kc = 0; kc < 4; kc++) {
            uint32_t bv[2][8][2];
#pragma unroll
            for (int p = 0; p < 2; p++)
#pragma unroll
                for (int na = 0; na < 4; na++) {
                    int row = kc * 16 + ((l >> 3) & 1) * 8 + (l & 7);
                    int col = na * 16 + (l >> 4) * 8;
                    uint32_t r4[4];
                    ldsm4t(r4, sb + RV(p) + (row * RST + col) * 2);
                    bv[p][na * 2][0] = r4[0]; bv[p][na * 2][1] = r4[1];
                    bv[p][na * 2 + 1][0] = r4[2]; bv[p][na * 2 + 1][1] = r4[3];
                }
#pragma unroll
            for (int ni = 0; ni < 8; ni++) mma_bf(oacc[ni], ash[kc], bv[0][ni]);
#pragma unroll
            for (int ni = 0; ni < 8; ni++) mma_bf(oacc[ni], ash[kc], bv[1][ni]);
#pragma unroll
            for (int ni = 0; ni < 8; ni++) mma_bf(oacc[ni], asl[kc], bv[0][ni]);
        }
    }

    // fused fp32-U state scan: state = sum_{c<ci} g128^(ci-1-c) * U_c
    __syncthreads();
    {
        const float g128 = exp2f(lg * 128.0f);
        const int row = tid >> 2;
        const int c0 = (tid & 3) * 16;
        float st[16];
#pragma unroll
        for (int j = 0; j < 16; j++) st[j] = 0.f;
        for (int c = 0; c < ci; c++) {
            const float* U = g_U + ((size_t)bh * NCHUNK + c) * HD * HD + row * HD + c0;
#pragma unroll
            for (int j = 0; j < 16; j++) st[j] = st[j] * g128 + U[j];
        }
#pragma unroll
        for (int j = 0; j < 16; j += 2) {
            bf16 h0 = __float2bfloat16(st[j]), h1 = __float2bfloat16(st[j + 1]);
            float l0 = st[j] - __bfloat162float(h0);
            float l1 = st[j + 1] - __bfloat162float(h1);
            bf162 hv; hv.x = h0; hv.y = h1;
            *(bf162*)(sm + RK(0) + (row * RST + c0 + j) * 2) = hv;
            bf162 lv; lv.x = __float2bfloat16(l0); lv.y = __float2bfloat16(l1);
            *(bf162*)(sm + RK(1) + (row * RST + c0 + j) * 2) = lv;
        }
    }
    __syncthreads();

    float cacc[8][4];
#pragma unroll
    for (int ni = 0; ni < 8; ni++)
#pragma unroll
        for (int q = 0; q < 4; q++) cacc[ni][q] = 0.f;
#pragma unroll
    for (int kc = 0; kc < 4; kc++) {
        uint32_t aq0[4], aq1[4];
        ldsm4(aq0, aq_addr_base + RQ(0) + kc * 32);
        ldsm4(aq1, aq_addr_base + RQ(1) + kc * 32);
        uint32_t bs[2][8][2];
#pragma unroll
        for (int p = 0; p < 2; p++)
#pragma unroll
            for (int na = 0; na < 4; na++) {
                int row = kc * 16 + ((l >> 3) & 1) * 8 + (l & 7);
                int col = na * 16 + (l >> 4) * 8;
                uint32_t r4[4];
                ldsm4t(r4, sb + RK(p) + (row * RST + col) * 2);
                bs[p][na * 2][0] = r4[0]; bs[p][na * 2][1] = r4[1];
                bs[p][na * 2 + 1][0] = r4[2]; bs[p][na * 2 + 1][1] = r4[3];
            }
#pragma unroll
        for (int ni = 0; ni < 8; ni++) mma_bf(cacc[ni], aq0, bs[0][ni]);
#pragma unroll
        for (int ni = 0; ni < 8; ni++) mma_bf(cacc[ni], aq0, bs[1][ni]);
#pragma unroll
        for (int ni = 0; ni < 8; ni++) mma_bf(cacc[ni], aq1, bs[0][ni]);
    }
    {
        const float w1 = 0.125f * exp2f(lg * (float)(il + 1));
        const float w2 = 0.125f * exp2f(lg * (float)(il + 9));
#pragma unroll
        for (int ni = 0; ni < 8; ni++) {
            oacc[ni][0] += w1 * cacc[ni][0];
            oacc[ni][1] += w1 * cacc[ni][1];
            oacc[ni][2] += w2 * cacc[ni][2];
            oacc[ni][3] += w2 * cacc[ni][3];
        }
    }

    // write O (fp32)
#pragma unroll
    for (int ni = 0; ni < 8; ni++) {
        int col = ni * 8 + 2 * tq;
        int r1 = t0 + il, r2 = r1 + 8;
        *(float2*)(g_O + (base + (size_t)r1 * HD + col)) = make_float2(oacc[ni][0], oacc[ni][1]);
        *(float2*)(g_O + (base + (size_t)r2 * HD + col)) = make_float2(oacc[ni][2], oacc[ni][3]);
    }

    // GroupNorm partial: block owns O[t0..t0+127][0..63] in oacc; fixed slot.
    {
        double s1 = 0.0, s2 = 0.0;
#pragma unroll
        for (int ni = 0; ni < 8; ni++)
#pragma unroll
            for (int q = 0; q < 4; q++) {
                float v = oacc[ni][q];
                s1 += v;
                s2 += (double)v * v;
            }
        double* r1 = (double*)(sm + RV(0));
        double* r2 = (double*)(sm + RV(0) + 2048);
        r1[tid] = s1; r2[tid] = s2;
        __syncthreads();
        for (int s = 128; s > 0; s >>= 1) {
            if (tid < s) { r1[tid] += r1[tid + s]; r2[tid] += r2[tid + s]; }
            __syncthreads();
        }
        if (tid == 0) g_gnp[bh * NCHUNK + ci] = make_double2(r1[0], r2[0]);
    }
}

// ---------------------------------------------------------------------------
// GroupNorm apply (reads 16 partials per bh)
// ---------------------------------------------------------------------------
__global__ __launch_bounds__(256) void gn_apply_kernel(const float* __restrict__ gnw,
                                                       const float* __restrict__ gnb) {
    const int part = blockIdx.x, bh = blockIdx.y;
    const int b = bh >> 4, h = bh & 15;
    double s1 = 0.0, s2 = 0.0;
#pragma unroll
    for (int p = 0; p < NCHUNK; p++) {
        double2 v = g_gnp[bh * NCHUNK + p];
        s1 += v.x; s2 += v.y;
    }
    const double n = (double)(NT * HD);
    double mud = s1 / n;
    double var = s2 / n - mud * mud;
    const float mu = (float)mud;
    const float rs = (float)(1.0 / sqrt(var + 1e-5));

    const float* bsrc = g_O + (size_t)bh * NT * HD;
    const int tid = threadIdx.x;
#pragma unroll 8
    for (int k = 0; k < 64; k++) {
        int i = part * 16384 + tid + 256 * k;
        int t = i >> 6, d = i & 63;
        int c = h * 64 + d;
        float v = (bsrc[i] - mu) * rs * gnw[c] + gnb[c];
        size_t idx = ((size_t)b * NT + t) * NC + c;
        bf16 hv = __float2bfloat16(v);
        g_Ynh[idx] = hv;
        g_Ynl[idx] = __float2bfloat16(v - __bfloat162float(hv));
    }
}

// ---------------------------------------------------------------------------
// Launch. Launch #4 = retention_chunk (profiled slot).
// ---------------------------------------------------------------------------
extern "C" void kernel_launch(void* const* d_in, const int* in_sizes, int n_in,
                              void* d_out, int out_size) {
    const float* x   = (const float*)d_in[0];
    const float* Wq  = (const float*)d_in[1];
    const float* Wk  = (const float*)d_in[2];
    const float* Wv  = (const float*)d_in[3];
    const float* Wo  = (const float*)d_in[4];
    const float* gnw = (const float*)d_in[5];
    const float* gnb = (const float*)d_in[6];
    float* out = (float*)d_out;

    cudaFuncSetAttribute(gemm_mma<0>, cudaFuncAttributeMaxDynamicSharedMemorySize, GEMM_SMEM);
    cudaFuncSetAttribute(gemm_mma<1>, cudaFuncAttributeMaxDynamicSharedMemorySize, GEMM_SMEM);
    cudaFuncSetAttribute(chunk_state_kernel, cudaFuncAttributeMaxDynamicSharedMemorySize, CHUNK_SMEM);
    cudaFuncSetAttribute(retention_chunk_kernel, cudaFuncAttributeMaxDynamicSharedMemorySize, RET_SMEM);

    split_all_kernel<<<(NX4 + 4 * NW4) / 256, 256>>>(
        (const float4*)x, (const float4*)Wq, (const float4*)Wk,
        (const float4*)Wv, (const float4*)Wo);                                 // 1
    gemm_mma<0><<<dim3(MTOT / 128, NC / 128, 3), 256, GEMM_SMEM>>>(nullptr);   // 2
    chunk_state_kernel<<<dim3(NCHUNK, NB * NH), 128, CHUNK_SMEM>>>();          // 3
    retention_chunk_kernel<<<dim3(NCHUNK, NB * NH), 256, RET_SMEM>>>();        // 4 (profiled)
    gn_apply_kernel<<<dim3(8, NB * NH), 256>>>(gnw, gnb);                      // 5
    gemm_mma<1><<<dim3(MTOT / 128, NC / 128, 1), 256, GEMM_SMEM>>>(out);       // 6
}

// round 13
// speedup vs baseline: 1.0480x; 1.0480x over previous
#include <cuda_runtime.h>
#include <cuda_bf16.h>
#include <math.h>
#include <cstdint>

#define NB 2
#define NT 2048
#define NH 16
#define HD 64
#define NC 1024
#define MTOT (NB*NT)   // 4096
#define NCHUNK 16      // T / 128

typedef __nv_bfloat16  bf16;
typedef __nv_bfloat162 bf162;

// ---------------------------------------------------------------------------
// Scratch (allocation-free rule: __device__ globals)
// ---------------------------------------------------------------------------
__device__ __align__(16) bf16 g_Xh[MTOT*NC],  g_Xl[MTOT*NC];
__device__ __align__(16) bf16 g_Wh[4*NC*NC],  g_Wl[4*NC*NC];
__device__ __align__(16) bf16 g_Qh[NB*NH*NT*HD], g_Ql[NB*NH*NT*HD];
__device__ __align__(16) bf16 g_Kh[NB*NH*NT*HD], g_Kl[NB*NH*NT*HD];
__device__ __align__(16) bf16 g_Vh[NB*NH*NT*HD], g_Vl[NB*NH*NT*HD];
__device__ __align__(16) float g_O[NB*NH*NT*HD];
__device__ __align__(16) bf16 g_Ynh[MTOT*NC], g_Ynl[MTOT*NC];
__device__ __align__(16) float g_U[NB*NH*NCHUNK*HD*HD];   // chunk summaries (fp32)
__device__ double2 g_gnp[NB*NH*NCHUNK];   // per-(bh,chunk) partial sums

// ---------------------------------------------------------------------------
// Helpers
// ---------------------------------------------------------------------------
__device__ __forceinline__ uint32_t smaddr(const void* p) {
    uint32_t a;
    asm("{ .reg .u64 t; cvta.to.shared.u64 t, %1; cvt.u32.u64 %0, t; }"
        : "=r"(a) : "l"(p));
    return a;
}
__device__ __forceinline__ void ldsm4(uint32_t r[4], uint32_t a) {
    asm volatile("ldmatrix.sync.aligned.m8n8.x4.shared.b16 {%0,%1,%2,%3}, [%4];"
        : "=r"(r[0]), "=r"(r[1]), "=r"(r[2]), "=r"(r[3]) : "r"(a));
}
__device__ __forceinline__ void ldsm4t(uint32_t r[4], uint32_t a) {
    asm volatile("ldmatrix.sync.aligned.m8n8.x4.trans.shared.b16 {%0,%1,%2,%3}, [%4];"
        : "=r"(r[0]), "=r"(r[1]), "=r"(r[2]), "=r"(r[3]) : "r"(a));
}
__device__ __forceinline__ void mma_bf(float c[4], const uint32_t a[4], const uint32_t b[2]) {
    asm volatile(
        "mma.sync.aligned.m16n8k16.row.col.f32.bf16.bf16.f32 "
        "{%0,%1,%2,%3}, {%4,%5,%6,%7}, {%8,%9}, {%0,%1,%2,%3};"
        : "+f"(c[0]), "+f"(c[1]), "+f"(c[2]), "+f"(c[3])
        : "r"(a[0]), "r"(a[1]), "r"(a[2]), "r"(a[3]), "r"(b[0]), "r"(b[1]));
}
__device__ __forceinline__ uint32_t pk2(float a, float b) {
    bf162 t = __floats2bfloat162_rn(a, b);
    return *reinterpret_cast<uint32_t*>(&t);
}
__device__ __forceinline__ float lg2gamma(int h) {
    double gamma = 1.0 - exp2(-5.0 - 0.5 * (double)h);
    return (float)log2(gamma);
}
__device__ __forceinline__ void cpa16(uint32_t s, const void* g) {
    asm volatile("cp.async.cg.shared.global [%0], [%1], 16;" :: "r"(s), "l"(g));
}
#define CP_COMMIT() asm volatile("cp.async.commit_group;" ::: "memory")
#define CP_WAIT0()  asm volatile("cp.async.wait_group 0;" ::: "memory")

__device__ __forceinline__ void split4(float4 v, uint2& hi, uint2& lo) {
    bf162 h0 = __floats2bfloat162_rn(v.x, v.y);
    bf162 h1 = __floats2bfloat162_rn(v.z, v.w);
    bf162 l0 = __floats2bfloat162_rn(v.x - __bfloat162float(h0.x),
                                     v.y - __bfloat162float(h0.y));
    bf162 l1 = __floats2bfloat162_rn(v.z - __bfloat162float(h1.x),
                                     v.w - __bfloat162float(h1.y));
    hi.x = *(uint32_t*)&h0; hi.y = *(uint32_t*)&h1;
    lo.x = *(uint32_t*)&l0; lo.y = *(uint32_t*)&l1;
}

// ---------------------------------------------------------------------------
// Fused split
// ---------------------------------------------------------------------------
#define NX4 (MTOT*NC/4)
#define NW4 (NC*NC/4)

__global__ __launch_bounds__(256) void split_all_kernel(
    const float4* __restrict__ x,  const float4* __restrict__ wq,
    const float4* __restrict__ wk, const float4* __restrict__ wv,
    const float4* __restrict__ wo)
{
    int i = blockIdx.x * 256 + threadIdx.x;
    uint2 hi, lo;
    if (i < NX4) {
        split4(x[i], hi, lo);
        *(uint2*)(g_Xh + 4 * (size_t)i) = hi;
        *(uint2*)(g_Xl + 4 * (size_t)i) = lo;
    } else {
        int j = i - NX4;
        int widx = j >> 18;
        int e = j & (NW4 - 1);
        const float4* w = (widx == 0) ? wq : (widx == 1) ? wk : (widx == 2) ? wv : wo;
        split4(w[e], hi, lo);
        *(uint2*)(g_Wh + (size_t)widx * NC * NC + 4 * (size_t)e) = hi;
        *(uint2*)(g_Wl + (size_t)widx * NC * NC + 4 * (size_t)e) = lo;
    }
}

// ---------------------------------------------------------------------------
// bf16x3 GEMM (R7/R10 config): BM=128, BN=128, warp tile 32x64, 2 CTAs/SM.
// ---------------------------------------------------------------------------
#define AST 40
#define KCH 32
#define SOA(buf,p) ((buf)*20480 + (p)*10240)
#define SOB(buf,p) (40960 + (buf)*20480 + (p)*10240)
#define GEMM_SMEM 81920

template<int MODE>
__global__ __launch_bounds__(256, 2) void gemm_mma(float* __restrict__ Cf) {
    extern __shared__ __align__(16) char sm[];
    const int tid = threadIdx.x, l = tid & 31, wid = tid >> 5;
    const int wm = wid & 3, wn = wid >> 2;
    const int r0 = blockIdx.x * 128, n0 = blockIdx.y * 128;
    const int z = blockIdx.z;
    const int wsel = (MODE == 0) ? z : 3;

    const bf16* Ah = (MODE == 0) ? g_Xh : g_Ynh;
    const bf16* Al = (MODE == 0) ? g_Xl : g_Ynl;
    const bf16* Wh = g_Wh + (size_t)wsel * NC * NC;
    const bf16* Wl = g_Wl + (size_t)wsel * NC * NC;
    const uint32_t sb = smaddr(sm);

    float acc[2][8][4];
#pragma unroll
    for (int mi = 0; mi < 2; mi++)
#pragma unroll
        for (int ni = 0; ni < 8; ni++)
#pragma unroll
            for (int q = 0; q < 4; q++) acc[mi][ni][q] = 0.f;

    auto load_chunk = [&](int kb, int buf) {
#pragma unroll
        for (int i = 0; i < 8; i++) {
            int j = tid + 256 * i;
            int row = (j >> 2) & 127, seg = j & 3, part = (j >> 9) & 1;
            if (j < 1024) {
                const bf16* src = (part ? Al : Ah) + (size_t)(r0 + row) * NC + kb + seg * 8;
                cpa16(sb + SOA(buf, part) + (row * AST + seg * 8) * 2, src);
            } else {
                const bf16* src = (part ? Wl : Wh) + (size_t)(n0 + row) * NC + kb + seg * 8;
                cpa16(sb + SOB(buf, part) + (row * AST + seg * 8) * 2, src);
            }
        }
    };

    load_chunk(0, 0);
    CP_COMMIT();

    for (int c = 0; c < KCH; c++) {
        const int buf = c & 1;
        CP_WAIT0();
        __syncthreads();
        if (c + 1 < KCH) {
            load_chunk((c + 1) * 32, buf ^ 1);
            CP_COMMIT();
        }
#pragma unroll
        for (int ks = 0; ks < 32; ks += 16) {
            uint32_t af[2][2][4];
#pragma unroll
            for (int p = 0; p < 2; p++)
#pragma unroll
                for (int mi = 0; mi < 2; mi++) {
                    int row = wm * 32 + mi * 16 + (l & 7) + ((l >> 3) & 1) * 8;
                    int col = ks + (l >> 4) * 8;
                    ldsm4(af[p][mi], sb + SOA(buf, p) + (row * AST + col) * 2);
                }
            {
                uint32_t b0[8][2];
#pragma unroll
                for (int na = 0; na < 4; na++) {
                    int row = wn * 64 + na * 16 + (l >> 4) * 8 + (l & 7);
                    int col = ks + ((l >> 3) & 1) * 8;
                    uint32_t r4[4];
                    ldsm4(r4, sb + SOB(buf, 0) + (row * AST + col) * 2);
                    b0[na * 2][0] = r4[0]; b0[na * 2][1] = r4[1];
                    b0[na * 2 + 1][0] = r4[2]; b0[na * 2 + 1][1] = r4[3];
                }
#pragma unroll
                for (int mi = 0; mi < 2; mi++)
#pragma unroll
                    for (int ni = 0; ni < 8; ni++) mma_bf(acc[mi][ni], af[0][mi], b0[ni]);
#pragma unroll
                for (int mi = 0; mi < 2; mi++)
#pragma unroll
                    for (int ni = 0; ni < 8; ni++) mma_bf(acc[mi][ni], af[1][mi], b0[ni]);
            }
            {
                uint32_t b1[8][2];
#pragma unroll
                for (int na = 0; na < 4; na++) {
                    int row = wn * 64 + na * 16 + (l >> 4) * 8 + (l & 7);
                    int col = ks + ((l >> 3) & 1) * 8;
                    uint32_t r4[4];
                    ldsm4(r4, sb + SOB(buf, 1) + (row * AST + col) * 2);
                    b1[na * 2][0] = r4[0]; b1[na * 2][1] = r4[1];
                    b1[na * 2 + 1][0] = r4[2]; b1[na * 2 + 1][1] = r4[3];
                }
#pragma unroll
                for (int mi = 0; mi < 2; mi++)
#pragma unroll
                    for (int ni = 0; ni < 8; ni++) mma_bf(acc[mi][ni], af[0][mi], b1[ni]);
            }
        }
    }

    const int g = l >> 2, tq = l & 3;
    bf16* oh = nullptr; bf16* ol = nullptr;
    if (MODE == 0) {
        oh = (z == 0) ? g_Qh : (z == 1) ? g_Kh : g_Vh;
        ol = (z == 0) ? g_Ql : (z == 1) ? g_Kl : g_Vl;
    }
#pragma unroll
    for (int mi = 0; mi < 2; mi++)
#pragma unroll
        for (int ni = 0; ni < 8; ni++) {
            int rbase = r0 + wm * 32 + mi * 16 + g;
            int n = n0 + wn * 64 + ni * 8 + 2 * tq;
#pragma unroll
            for (int rr = 0; rr < 2; rr++) {
                int row = rbase + rr * 8;
                float v0 = acc[mi][ni][rr * 2 + 0];
                float v1 = acc[mi][ni][rr * 2 + 1];
                if (MODE == 0) {
                    int b = row >> 11, t = row & (NT - 1);
                    int hh = n >> 6, d = n & 63;
                    size_t idx = (((size_t)b * NH + hh) * NT + t) * HD + d;
                    bf16 h0 = __float2bfloat16(v0);
                    bf16 h1 = __float2bfloat16(v1);
                    bf162 hv; hv.x = h0; hv.y = h1;
                    bf162 lv;
                    lv.x = __float2bfloat16(v0 - __bfloat162float(h0));
                    lv.y = __float2bfloat16(v1 - __bfloat162float(h1));
                    *(bf162*)(oh + idx) = hv;
                    *(bf162*)(ol + idx) = lv;
                } else {
                    *(float2*)(Cf + (size_t)row * NC + n) = make_float2(v0, v1);
                }
            }
        }
}

// ---------------------------------------------------------------------------
// Phase A: per-chunk KV summary -> fp32 U
// ---------------------------------------------------------------------------
#define CST 72
#define CWK(p) ((p)*18432)
#define CV(p)  (36864 + (p)*18432)
#define CHUNK_SMEM 73728

__global__ __launch_bounds__(128) void chunk_state_kernel() {
    extern __shared__ __align__(16) char sm[];
    const int tid = threadIdx.x, l = tid & 31, wid = tid >> 5;
    const int ci = blockIdx.x, bh = blockIdx.y, h = bh & (NH - 1);
    const float lg = lg2gamma(h);
    const uint32_t sb = smaddr(sm);
    const size_t base = (size_t)bh * NT * HD + (size_t)ci * 128 * HD;

    {
        const int j = tid;
        const float w = exp2f(lg * (float)(127 - j));
        const bf16* Kh = g_Kh + base + (size_t)j * HD;
        const bf16* Kl = g_Kl + base + (size_t)j * HD;
        const bf16* Vh = g_Vh + base + (size_t)j * HD;
        const bf16* Vl = g_Vl + base + (size_t)j * HD;
#pragma unroll
        for (int seg = 0; seg < 8; seg++) {
            uint4 khv = *(const uint4*)(Kh + seg * 8);
            uint4 klv = *(const uint4*)(Kl + seg * 8);
            const bf162* kh2 = (const bf162*)&khv;
            const bf162* kl2 = (const bf162*)&klv;
            uint32_t oh[4], ol[4];
#pragma unroll
            for (int q = 0; q < 4; q++) {
                float f0 = __bfloat162float(kh2[q].x) + __bfloat162float(kl2[q].x);
                float f1 = __bfloat162float(kh2[q].y) + __bfloat162float(kl2[q].y);
                f0 *= w; f1 *= w;
                bf16 h0 = __float2bfloat16(f0), h1 = __float2bfloat16(f1);
                float r0 = f0 - __bfloat162float(h0);
                float r1 = f1 - __bfloat162float(h1);
                ol[q] = pk2(r0, r1);
                bf162 hv; hv.x = h0; hv.y = h1;
                oh[q] = *(uint32_t*)&hv;
            }
            *(uint4*)(sm + CWK(0) + (j * CST + seg * 8) * 2) = *(uint4*)oh;
            *(uint4*)(sm + CWK(1) + (j * CST + seg * 8) * 2) = *(uint4*)ol;
            *(uint4*)(sm + CV(0) + (j * CST + seg * 8) * 2) = *(const uint4*)(Vh + seg * 8);
            *(uint4*)(sm + CV(1) + (j * CST + seg * 8) * 2) = *(const uint4*)(Vl + seg * 8);
        }
    }
    __syncthreads();

    float acc[8][4];
#pragma unroll
    for (int ni = 0; ni < 8; ni++)
#pragma unroll
        for (int q = 0; q < 4; q++) acc[ni][q] = 0.f;

#pragma unroll
    for (int ks = 0; ks < 8; ks++) {
        uint32_t ah[4], al[4];
        {
            int row = ks * 16 + (l & 7) + ((l >> 4) & 1) * 8;
            int col = 16 * wid + ((l >> 3) & 1) * 8;
            ldsm4t(ah, sb + CWK(0) + (row * CST + col) * 2);
            ldsm4t(al, sb + CWK(1) + (row * CST + col) * 2);
        }
        uint32_t bv[2][8][2];
#pragma unroll
        for (int p = 0; p < 2; p++)
#pragma unroll
            for (int na = 0; na < 4; na++) {
                int row = ks * 16 + ((l >> 3) & 1) * 8 + (l & 7);
                int col = na * 16 + (l >> 4) * 8;
                uint32_t r4[4];
                ldsm4t(r4, sb + CV(p) + (row * CST + col) * 2);
                bv[p][na * 2][0] = r4[0]; bv[p][na * 2][1] = r4[1];
                bv[p][na * 2 + 1][0] = r4[2]; bv[p][na * 2 + 1][1] = r4[3];
            }
#pragma unroll
        for (int ni = 0; ni < 8; ni++) mma_bf(acc[ni], ah, bv[0][ni]);
#pragma unroll
        for (int ni = 0; ni < 8; ni++) mma_bf(acc[ni], ah, bv[1][ni]);
#pragma unroll
        for (int ni = 0; ni < 8; ni++) mma_bf(acc[ni], al, bv[0][ni]);
    }

    float* U = g_U + ((size_t)bh * NCHUNK + ci) * HD * HD;
    const int g = l >> 2, tq = l & 3;
#pragma unroll
    for (int ni = 0; ni < 8; ni++) {
        int col = ni * 8 + 2 * tq;
        int row1 = 16 * wid + g, row2 = row1 + 8;
        *(float2*)(U + row1 * HD + col) = make_float2(acc[ni][0], acc[ni][1]);
        *(float2*)(U + row2 * HD + col) = make_float2(acc[ni][2], acc[ni][3]);
    }
}

// ---------------------------------------------------------------------------
// Phase C: intra-chunk quadratic + fused fp32-U state scan + GN partial (fp32).
// ---------------------------------------------------------------------------
#define RST 72
#define RQ(p)  ((p)*18432)
#define RK(p)  (36864 + (p)*9216)
#define RV(p)  (55296 + (p)*9216)
#define RDW    73728
#define RET_SMEM 74752

__global__ __launch_bounds__(256, 2) void retention_chunk_kernel() {
    extern __shared__ __align__(16) char sm[];
    float* dw = (float*)(sm + RDW);
    const int tid = threadIdx.x, l = tid & 31, wid = tid >> 5;
    const int bh = blockIdx.y, h = bh & (NH - 1);
    const int ci = blockIdx.x;
    const int t0 = ci * 128;
    const float lg = lg2gamma(h);
    const uint32_t sb = smaddr(sm);
    const size_t base = (size_t)bh * NT * HD;

#pragma unroll
    for (int p = 0; p < 2; p++) {
        const bf16* Qp = (p ? g_Ql : g_Qh) + base + (size_t)t0 * HD;
#pragma unroll
        for (int i = 0; i < 4; i++) {
            int flat = tid + 256 * i;
            int row = flat >> 3, seg = flat & 7;
            uint4 v = *(const uint4*)(Qp + (size_t)row * HD + seg * 8);
            *(uint4*)(sm + RQ(p) + (row * RST + seg * 8) * 2) = v;
        }
    }
    __syncthreads();

    const uint32_t aq_addr_base = sb + ((wid * 16 + (l & 7) + ((l >> 3) & 1) * 8) * RST
                                        + (l >> 4) * 8) * 2;

    float oacc[8][4];
#pragma unroll
    for (int ni = 0; ni < 8; ni++)
#pragma unroll
        for (int q = 0; q < 4; q++) oacc[ni][q] = 0.f;

    const int g = l >> 2, tq = l & 3;
    const int il = 16 * wid + g;

    for (int s0 = t0; s0 <= t0 + 64; s0 += 64) {
        __syncthreads();
#pragma unroll
        for (int p = 0; p < 2; p++) {
            const bf16* Kp = (p ? g_Kl : g_Kh) + base + (size_t)s0 * HD;
            const bf16* Vp = (p ? g_Vl : g_Vh) + base + (size_t)s0 * HD;
#pragma unroll
            for (int i = 0; i < 2; i++) {
                int flat = tid + 256 * i;
                int row = flat >> 3, seg = flat & 7;
                uint4 kv = *(const uint4*)(Kp + (size_t)row * HD + seg * 8);
                *(uint4*)(sm + RK(p) + (row * RST + seg * 8) * 2) = kv;
                uint4 vv = *(const uint4*)(Vp + (size_t)row * HD + seg * 8);
                *(uint4*)(sm + RV(p) + (row * RST + seg * 8) * 2) = vv;
            }
        }
        if (tid < 192) {
            int diff = t0 - s0 - 63 + tid;
            dw[tid] = (diff >= 0) ? 0.125f * exp2f(lg * (float)diff) : 0.f;
        }
        __syncthreads();

        float sacc[8][4];
#pragma unroll
        for (int ni = 0; ni < 8; ni++)
#pragma unroll
            for (int q = 0; q < 4; q++) sacc[ni][q] = 0.f;
#pragma unroll
        for (int kc = 0; kc < 4; kc++) {
            uint32_t aq0[4], aq1[4];
            ldsm4(aq0, aq_addr_base + RQ(0) + kc * 32);
            ldsm4(aq1, aq_addr_base + RQ(1) + kc * 32);
            uint32_t bk[2][8][2];
#pragma unroll
            for (int p = 0; p < 2; p++)
#pragma unroll
                for (int na = 0; na < 4; na++) {
                    int row = na * 16 + (l >> 4) * 8 + (l & 7);
                    int col = kc * 16 + ((l >> 3) & 1) * 8;
                    uint32_t r4[4];
                    ldsm4(r4, sb + RK(p) + (row * RST + col) * 2);
                    bk[p][na * 2][0] = r4[0]; bk[p][na * 2][1] = r4[1];
                    bk[p][na * 2 + 1][0] = r4[2]; bk[p][na * 2 + 1][1] = r4[3];
                }
#pragma unroll
            for (int ni = 0; ni < 8; ni++) mma_bf(sacc[ni], aq0, bk[0][ni]);
#pragma unroll
            for (int ni = 0; ni < 8; ni++) mma_bf(sacc[ni], aq0, bk[1][ni]);
#pragma unroll
            for (int ni = 0; ni < 8; ni++) mma_bf(sacc[ni], aq1, bk[0][ni]);
        }

#pragma unroll
        for (int ni = 0; ni < 8; ni++) {
            int jb = ni * 8 + 2 * tq;
            sacc[ni][0] *= dw[63 + il - jb];
            sacc[ni][1] *= dw[63 + il - (jb + 1)];
            sacc[ni][2] *= dw[63 + il + 8 - jb];
            sacc[ni][3] *= dw[63 + il + 8 - (jb + 1)];
        }

        uint32_t ash[4][4], asl[4][4];
#pragma unroll
        for (int kc = 0; kc < 4; kc++) {
            const float* e0 = sacc[2 * kc];
            const float* e1 = sacc[2 * kc + 1];
            float src[8] = {e0[0], e0[1], e0[2], e0[3], e1[0], e1[1], e1[2], e1[3]};
            float hv[8], lv[8];
#pragma unroll
            for (int q = 0; q < 8; q++) {
                bf16 hb = __float2bfloat16(src[q]);
                hv[q] = __bfloat162float(hb);
                lv[q] = src[q] - hv[q];
            }
            ash[kc][0] = pk2(hv[0], hv[1]); ash[kc][1] = pk2(hv[2], hv[3]);
            ash[kc][2] = pk2(hv[4], hv[5]); ash[kc][3] = pk2(hv[6], hv[7]);
            asl[kc][0] = pk2(lv[0], lv[1]); asl[kc][1] = pk2(lv[2], lv[3]);
            asl[kc][2] = pk2(lv[4], lv[5]); asl[kc][3] = pk2(lv[6], lv[7]);
        }

#pragma unroll
        for (int kc = 0; kc < 4; kc++) {
            uint32_t bv[2][8][2];
#pragma unroll
            for (int p = 0; p < 2; p++)
#pragma unroll
                for (int na = 0; na < 4; na++) {
                    int row = kc * 16 + ((l >> 3) & 1) * 8 + (l & 7);
                    int col = na * 16 + (l >> 4) * 8;
                    uint32_t r4[4];
                    ldsm4t(r4, sb + RV(p) + (row * RST + col) * 2);
                    bv[p][na * 2][0] = r4[0]; bv[p][na * 2][1] = r4[1];
                    bv[p][na * 2 + 1][0] = r4[2]; bv[p][na * 2 + 1][1] = r4[3];
                }
#pragma unroll
            for (int ni = 0; ni < 8; ni++) mma_bf(oacc[ni], ash[kc], bv[0][ni]);
#pragma unroll
            for (int ni = 0; ni < 8; ni++) mma_bf(oacc[ni], ash[kc], bv[1][ni]);
#pragma unroll
            for (int ni = 0; ni < 8; ni++) mma_bf(oacc[ni], asl[kc], bv[0][ni]);
        }
    }

    // fused fp32-U state scan: state = sum_{c<ci} g128^(ci-1-c) * U_c
    __syncthreads();
    {
        const float g128 = exp2f(lg * 128.0f);
        const int row = tid >> 2;
        const int c0 = (tid & 3) * 16;
        float st[16];
#pragma unroll
        for (int j = 0; j < 16; j++) st[j] = 0.f;
        for (int c = 0; c < ci; c++) {
            const float* U = g_U + ((size_t)bh * NCHUNK + c) * HD * HD + row * HD + c0;
#pragma unroll
            for (int j = 0; j < 16; j++) st[j] = st[j] * g128 + U[j];
        }
#pragma unroll
        for (int j = 0; j < 16; j += 2) {
            bf16 h0 = __float2bfloat16(st[j]), h1 = __float2bfloat16(st[j + 1]);
            float l0 = st[j] - __bfloat162float(h0);
            float l1 = st[j + 1] - __bfloat162float(h1);
            bf162 hv; hv.x = h0; hv.y = h1;
            *(bf162*)(sm + RK(0) + (row * RST + c0 + j) * 2) = hv;
            bf162 lv; lv.x = __float2bfloat16(l0); lv.y = __float2bfloat16(l1);
            *(bf162*)(sm + RK(1) + (row * RST + c0 + j) * 2) = lv;
        }
    }
    __syncthreads();

    float cacc[8][4];
#pragma unroll
    for (int ni = 0; ni < 8; ni++)
#pragma unroll
        for (int q = 0; q < 4; q++) cacc[ni][q] = 0.f;
#pragma unroll
    for (int kc = 0; kc < 4; kc++) {
        uint32_t aq0[4], aq1[4];
        ldsm4(aq0, aq_addr_base + RQ(0) + kc * 32);
        ldsm4(aq1, aq_addr_base + RQ(1) + kc * 32);
        uint32_t bs[2][8][2];
#pragma unroll
        for (int p = 0; p < 2; p++)
#pragma unroll
            for (int na = 0; na < 4; na++) {
                int row = kc * 16 + ((l >> 3) & 1) * 8 + (l & 7);
                int col = na * 16 + (l >> 4) * 8;
                uint32_t r4[4];
                ldsm4t(r4, sb + RK(p) + (row * RST + col) * 2);
                bs[p][na * 2][0] = r4[0]; bs[p][na * 2][1] = r4[1];
                bs[p][na * 2 + 1][0] = r4[2]; bs[p][na * 2 + 1][1] = r4[3];
            }
#pragma unroll
        for (int ni = 0; ni < 8; ni++) mma_bf(cacc[ni], aq0, bs[0][ni]);
#pragma unroll
        for (int ni = 0; ni < 8; ni++) mma_bf(cacc[ni], aq0, bs[1][ni]);
#pragma unroll
        for (int ni = 0; ni < 8; ni++) mma_bf(cacc[ni], aq1, bs[0][ni]);
    }
    {
        const float w1 = 0.125f * exp2f(lg * (float)(il + 1));
        const float w2 = 0.125f * exp2f(lg * (float)(il + 9));
#pragma unroll
        for (int ni = 0; ni < 8; ni++) {
            oacc[ni][0] += w1 * cacc[ni][0];
            oacc[ni][1] += w1 * cacc[ni][1];
            oacc[ni][2] += w2 * cacc[ni][2];
            oacc[ni][3] += w2 * cacc[ni][3];
        }
    }

    // write O (fp32)
#pragma unroll
    for (int ni = 0; ni < 8; ni++) {
        int col = ni * 8 + 2 * tq;
        int r1 = t0 + il, r2 = r1 + 8;
        *(float2*)(g_O + (base + (size_t)r1 * HD + col)) = make_float2(oacc[ni][0], oacc[ni][1]);
        *(float2*)(g_O + (base + (size_t)r2 * HD + col)) = make_float2(oacc[ni][2], oacc[ni][3]);
    }

    // GroupNorm partial in fp32: per-thread accumulate + warp butterfly,
    // doubles only for the 8 per-warp partials (deterministic).
    {
        float s1 = 0.f, s2 = 0.f;
#pragma unroll
        for (int ni = 0; ni < 8; ni++)
#pragma unroll
            for (int q = 0; q < 4; q++) {
                float v = oacc[ni][q];
                s1 += v;
                s2 += v * v;
            }
#pragma unroll
        for (int o = 16; o > 0; o >>= 1) {
            s1 += __shfl_xor_sync(0xFFFFFFFFu, s1, o);
            s2 += __shfl_xor_sync(0xFFFFFFFFu, s2, o);
        }
        float* w1p = (float*)(sm + RV(0));
        float* w2p = (float*)(sm + RV(0) + 64);
        if (l == 0) { w1p[wid] = s1; w2p[wid] = s2; }
        __syncthreads();
        if (tid == 0) {
            double a = 0.0, b2 = 0.0;
#pragma unroll
            for (int w = 0; w < 8; w++) { a += (double)w1p[w]; b2 += (double)w2p[w]; }
            g_gnp[bh * NCHUNK + ci] = make_double2(a, b2);
        }
    }
}

// ---------------------------------------------------------------------------
// GroupNorm apply (reads 16 partials per bh)
// ---------------------------------------------------------------------------
__global__ __launch_bounds__(256) void gn_apply_kernel(const float* __restrict__ gnw,
                                                       const float* __restrict__ gnb) {
    const int part = blockIdx.x, bh = blockIdx.y;
    const int b = bh >> 4, h = bh & 15;
    double s1 = 0.0, s2 = 0.0;
#pragma unroll
    for (int p = 0; p < NCHUNK; p++) {
        double2 v = g_gnp[bh * NCHUNK + p];
        s1 += v.x; s2 += v.y;
    }
    const double n = (double)(NT * HD);
    double mud = s1 / n;
    double var = s2 / n - mud * mud;
    const float mu = (float)mud;
    const float rs = (float)(1.0 / sqrt(var + 1e-5));

    const float* bsrc = g_O + (size_t)bh * NT * HD;
    const int tid = threadIdx.x;
#pragma unroll 8
    for (int k = 0; k < 64; k++) {
        int i = part * 16384 + tid + 256 * k;
        int t = i >> 6, d = i & 63;
        int c = h * 64 + d;
        float v = (bsrc[i] - mu) * rs * gnw[c] + gnb[c];
        size_t idx = ((size_t)b * NT + t) * NC + c;
        bf16 hv = __float2bfloat16(v);
        g_Ynh[idx] = hv;
        g_Ynl[idx] = __float2bfloat16(v - __bfloat162float(hv));
    }
}

// ---------------------------------------------------------------------------
// Launch. Launch #4 = retention_chunk (profiled slot).
// ---------------------------------------------------------------------------
extern "C" void kernel_launch(void* const* d_in, const int* in_sizes, int n_in,
                              void* d_out, int out_size) {
    const float* x   = (const float*)d_in[0];
    const float* Wq  = (const float*)d_in[1];
    const float* Wk  = (const float*)d_in[2];
    const float* Wv  = (const float*)d_in[3];
    const float* Wo  = (const float*)d_in[4];
    const float* gnw = (const float*)d_in[5];
    const float* gnb = (const float*)d_in[6];
    float* out = (float*)d_out;

    cudaFuncSetAttribute(gemm_mma<0>, cudaFuncAttributeMaxDynamicSharedMemorySize, GEMM_SMEM);
    cudaFuncSetAttribute(gemm_mma<1>, cudaFuncAttributeMaxDynamicSharedMemorySize, GEMM_SMEM);
    cudaFuncSetAttribute(chunk_state_kernel, cudaFuncAttributeMaxDynamicSharedMemorySize, CHUNK_SMEM);
    cudaFuncSetAttribute(retention_chunk_kernel, cudaFuncAttributeMaxDynamicSharedMemorySize, RET_SMEM);

    split_all_kernel<<<(NX4 + 4 * NW4) / 256, 256>>>(
        (const float4*)x, (const float4*)Wq, (const float4*)Wk,
        (const float4*)Wv, (const float4*)Wo);                                 // 1
    gemm_mma<0><<<dim3(MTOT / 128, NC / 128, 3), 256, GEMM_SMEM>>>(nullptr);   // 2
    chunk_state_kernel<<<dim3(NCHUNK, NB * NH), 128, CHUNK_SMEM>>>();          // 3
    retention_chunk_kernel<<<dim3(NCHUNK, NB * NH), 256, RET_SMEM>>>();        // 4 (profiled)
    gn_apply_kernel<<<dim3(8, NB * NH), 256>>>(gnw, gnb);                      // 5
    gemm_mma<1><<<dim3(MTOT / 128, NC / 128, 1), 256, GEMM_SMEM>>>(out);       // 6
}

// round 14
// speedup vs baseline: 1.3286x; 1.2678x over previous
#include <cuda_runtime.h>
#include <cuda_bf16.h>
#include <cuda_fp16.h>
#include <math.h>
#include <cstdint>

#define NB 2
#define NT 2048
#define NH 16
#define HD 64
#define NC 1024
#define MTOT (NB*NT)   // 4096
#define NCHUNK 16      // T / 128

typedef __nv_bfloat16  bf16;
typedef __nv_bfloat162 bf162;

// ---------------------------------------------------------------------------
// Scratch (allocation-free rule: __device__ globals)
// ---------------------------------------------------------------------------
__device__ __align__(16) __half g_Xh[MTOT*NC], g_Xl[MTOT*NC];   // x split (fp16)
__device__ __align__(16) __half g_W16[4*NC*NC];                  // weights (fp16 single)
__device__ __align__(16) bf16 g_Qh[NB*NH*NT*HD], g_Ql[NB*NH*NT*HD];
__device__ __align__(16) bf16 g_Kh[NB*NH*NT*HD], g_Kl[NB*NH*NT*HD];
__device__ __align__(16) bf16 g_Vh[NB*NH*NT*HD], g_Vl[NB*NH*NT*HD];
__device__ __align__(16) float g_O[NB*NH*NT*HD];
__device__ __align__(16) __half g_Ynh[MTOT*NC], g_Ynl[MTOT*NC]; // GN out split (fp16)
__device__ __align__(16) float g_U[NB*NH*NCHUNK*HD*HD];
__device__ double2 g_gnp[NB*NH*NCHUNK];

// ---------------------------------------------------------------------------
// Helpers
// ---------------------------------------------------------------------------
__device__ __forceinline__ uint32_t smaddr(const void* p) {
    uint32_t a;
    asm("{ .reg .u64 t; cvta.to.shared.u64 t, %1; cvt.u32.u64 %0, t; }"
        : "=r"(a) : "l"(p));
    return a;
}
__device__ __forceinline__ void ldsm4(uint32_t r[4], uint32_t a) {
    asm volatile("ldmatrix.sync.aligned.m8n8.x4.shared.b16 {%0,%1,%2,%3}, [%4];"
        : "=r"(r[0]), "=r"(r[1]), "=r"(r[2]), "=r"(r[3]) : "r"(a));
}
__device__ __forceinline__ void ldsm4t(uint32_t r[4], uint32_t a) {
    asm volatile("ldmatrix.sync.aligned.m8n8.x4.trans.shared.b16 {%0,%1,%2,%3}, [%4];"
        : "=r"(r[0]), "=r"(r[1]), "=r"(r[2]), "=r"(r[3]) : "r"(a));
}
__device__ __forceinline__ void mma_bf(float c[4], const uint32_t a[4], const uint32_t b[2]) {
    asm volatile(
        "mma.sync.aligned.m16n8k16.row.col.f32.bf16.bf16.f32 "
        "{%0,%1,%2,%3}, {%4,%5,%6,%7}, {%8,%9}, {%0,%1,%2,%3};"
        : "+f"(c[0]), "+f"(c[1]), "+f"(c[2]), "+f"(c[3])
        : "r"(a[0]), "r"(a[1]), "r"(a[2]), "r"(a[3]), "r"(b[0]), "r"(b[1]));
}
__device__ __forceinline__ void mma_f16(float c[4], const uint32_t a[4], const uint32_t b[2]) {
    asm volatile(
        "mma.sync.aligned.m16n8k16.row.col.f32.f16.f16.f32 "
        "{%0,%1,%2,%3}, {%4,%5,%6,%7}, {%8,%9}, {%0,%1,%2,%3};"
        : "+f"(c[0]), "+f"(c[1]), "+f"(c[2]), "+f"(c[3])
        : "r"(a[0]), "r"(a[1]), "r"(a[2]), "r"(a[3]), "r"(b[0]), "r"(b[1]));
}
__device__ __forceinline__ uint32_t pk2(float a, float b) {
    bf162 t = __floats2bfloat162_rn(a, b);
    return *reinterpret_cast<uint32_t*>(&t);
}
__device__ __forceinline__ float lg2gamma(int h) {
    double gamma = 1.0 - exp2(-5.0 - 0.5 * (double)h);
    return (float)log2(gamma);
}
__device__ __forceinline__ void cpa16(uint32_t s, const void* g) {
    asm volatile("cp.async.cg.shared.global [%0], [%1], 16;" :: "r"(s), "l"(g));
}
#define CP_COMMIT() asm volatile("cp.async.commit_group;" ::: "memory")
#define CP_WAIT0()  asm volatile("cp.async.wait_group 0;" ::: "memory")

// split fp32x4 -> fp16 hi/lo pairs
__device__ __forceinline__ void split4h(float4 v, uint2& hi, uint2& lo) {
    __half2 h0 = __floats2half2_rn(v.x, v.y);
    __half2 h1 = __floats2half2_rn(v.z, v.w);
    float2 f0 = __half22float2(h0), f1 = __half22float2(h1);
    __half2 l0 = __floats2half2_rn(v.x - f0.x, v.y - f0.y);
    __half2 l1 = __floats2half2_rn(v.z - f1.x, v.w - f1.y);
    hi.x = *(uint32_t*)&h0; hi.y = *(uint32_t*)&h1;
    lo.x = *(uint32_t*)&l0; lo.y = *(uint32_t*)&l1;
}

// ---------------------------------------------------------------------------
// Fused split: x -> fp16 hi/lo; W -> fp16 single.
// ---------------------------------------------------------------------------
#define NX4 (MTOT*NC/4)
#define NW4 (NC*NC/4)

__global__ __launch_bounds__(256) void split_all_kernel(
    const float4* __restrict__ x,  const float4* __restrict__ wq,
    const float4* __restrict__ wk, const float4* __restrict__ wv,
    const float4* __restrict__ wo)
{
    int i = blockIdx.x * 256 + threadIdx.x;
    if (i < NX4) {
        uint2 hi, lo;
        split4h(x[i], hi, lo);
        *(uint2*)(g_Xh + 4 * (size_t)i) = hi;
        *(uint2*)(g_Xl + 4 * (size_t)i) = lo;
    } else {
        int j = i - NX4;
        int widx = j >> 18;
        int e = j & (NW4 - 1);
        const float4* w = (widx == 0) ? wq : (widx == 1) ? wk : (widx == 2) ? wv : wo;
        float4 v = w[e];
        __half2 a = __floats2half2_rn(v.x, v.y);
        __half2 b = __floats2half2_rn(v.z, v.w);
        uint2 o; o.x = *(uint32_t*)&a; o.y = *(uint32_t*)&b;
        *(uint2*)(g_W16 + (size_t)widx * NC * NC + 4 * (size_t)e) = o;
    }
}

// ---------------------------------------------------------------------------
// fp16 2-term GEMM: C = A*W^T with A = hi+lo (fp16 pair), W fp16 single.
// BM=128, BN=128, warp tile 32x64, 8 warps, 2 CTAs/SM, cp.async 2-stage.
// ---------------------------------------------------------------------------
#define AST 40
#define KCH 32
#define SOA(buf,p) ((buf)*30720 + (p)*10240)
#define SOB(buf)   ((buf)*30720 + 20480)
#define GEMM_SMEM 61440

template<int MODE>
__global__ __launch_bounds__(256, 2) void gemm_mma(float* __restrict__ Cf) {
    extern __shared__ __align__(16) char sm[];
    const int tid = threadIdx.x, l = tid & 31, wid = tid >> 5;
    const int wm = wid & 3, wn = wid >> 2;
    const int r0 = blockIdx.x * 128, n0 = blockIdx.y * 128;
    const int z = blockIdx.z;
    const int wsel = (MODE == 0) ? z : 3;

    const __half* Ah = (MODE == 0) ? g_Xh : g_Ynh;
    const __half* Al = (MODE == 0) ? g_Xl : g_Ynl;
    const __half* W  = g_W16 + (size_t)wsel * NC * NC;
    const uint32_t sb = smaddr(sm);

    float acc[2][8][4];
#pragma unroll
    for (int mi = 0; mi < 2; mi++)
#pragma unroll
        for (int ni = 0; ni < 8; ni++)
#pragma unroll
            for (int q = 0; q < 4; q++) acc[mi][ni][q] = 0.f;

    // one chunk = A 1024 x16B (2 parts) + B 512 x16B = 1536 -> 6 per thread
    auto load_chunk = [&](int kb, int buf) {
#pragma unroll
        for (int i = 0; i < 6; i++) {
            int j = tid + 256 * i;
            if (j < 1024) {
                int part = j >> 9, row = (j >> 2) & 127, seg = j & 3;
                const __half* src = (part ? Al : Ah) + (size_t)(r0 + row) * NC + kb + seg * 8;
                cpa16(sb + SOA(buf, part) + (row * AST + seg * 8) * 2, src);
            } else {
                int jj = j - 1024;
                int row = jj >> 2, seg = jj & 3;
                const __half* src = W + (size_t)(n0 + row) * NC + kb + seg * 8;
                cpa16(sb + SOB(buf) + (row * AST + seg * 8) * 2, src);
            }
        }
    };

    load_chunk(0, 0);
    CP_COMMIT();

    for (int c = 0; c < KCH; c++) {
        const int buf = c & 1;
        CP_WAIT0();
        __syncthreads();
        if (c + 1 < KCH) {
            load_chunk((c + 1) * 32, buf ^ 1);
            CP_COMMIT();
        }
#pragma unroll
        for (int ks = 0; ks < 32; ks += 16) {
            uint32_t af[2][2][4];
#pragma unroll
            for (int p = 0; p < 2; p++)
#pragma unroll
                for (int mi = 0; mi < 2; mi++) {
                    int row = wm * 32 + mi * 16 + (l & 7) + ((l >> 3) & 1) * 8;
                    int col = ks + (l >> 4) * 8;
                    ldsm4(af[p][mi], sb + SOA(buf, p) + (row * AST + col) * 2);
                }
            uint32_t bfr[8][2];
#pragma unroll
            for (int na = 0; na < 4; na++) {
                int row = wn * 64 + na * 16 + (l >> 4) * 8 + (l & 7);
                int col = ks + ((l >> 3) & 1) * 8;
                uint32_t r4[4];
                ldsm4(r4, sb + SOB(buf) + (row * AST + col) * 2);
                bfr[na * 2][0] = r4[0]; bfr[na * 2][1] = r4[1];
                bfr[na * 2 + 1][0] = r4[2]; bfr[na * 2 + 1][1] = r4[3];
            }
#pragma unroll
            for (int mi = 0; mi < 2; mi++)
#pragma unroll
                for (int ni = 0; ni < 8; ni++) mma_f16(acc[mi][ni], af[0][mi], bfr[ni]);
#pragma unroll
            for (int mi = 0; mi < 2; mi++)
#pragma unroll
                for (int ni = 0; ni < 8; ni++) mma_f16(acc[mi][ni], af[1][mi], bfr[ni]);
        }
    }

    const int g = l >> 2, tq = l & 3;
    bf16* oh = nullptr; bf16* ol = nullptr;
    if (MODE == 0) {
        oh = (z == 0) ? g_Qh : (z == 1) ? g_Kh : g_Vh;
        ol = (z == 0) ? g_Ql : (z == 1) ? g_Kl : g_Vl;
    }
#pragma unroll
    for (int mi = 0; mi < 2; mi++)
#pragma unroll
        for (int ni = 0; ni < 8; ni++) {
            int rbase = r0 + wm * 32 + mi * 16 + g;
            int n = n0 + wn * 64 + ni * 8 + 2 * tq;
#pragma unroll
            for (int rr = 0; rr < 2; rr++) {
                int row = rbase + rr * 8;
                float v0 = acc[mi][ni][rr * 2 + 0];
                float v1 = acc[mi][ni][rr * 2 + 1];
                if (MODE == 0) {
                    int b = row >> 11, t = row & (NT - 1);
                    int hh = n >> 6, d = n & 63;
                    size_t idx = (((size_t)b * NH + hh) * NT + t) * HD + d;
                    bf16 h0 = __float2bfloat16(v0);
                    bf16 h1 = __float2bfloat16(v1);
                    bf162 hv; hv.x = h0; hv.y = h1;
                    bf162 lv;
                    lv.x = __float2bfloat16(v0 - __bfloat162float(h0));
                    lv.y = __float2bfloat16(v1 - __bfloat162float(h1));
                    *(bf162*)(oh + idx) = hv;
                    *(bf162*)(ol + idx) = lv;
                } else {
                    *(float2*)(Cf + (size_t)row * NC + n) = make_float2(v0, v1);
                }
            }
        }
}

// ---------------------------------------------------------------------------
// Phase A: per-chunk KV summary -> fp32 U (bf16x3 internally, unchanged)
// ---------------------------------------------------------------------------
#define CST 72
#define CWK(p) ((p)*18432)
#define CV(p)  (36864 + (p)*18432)
#define CHUNK_SMEM 73728

__global__ __launch_bounds__(128) void chunk_state_kernel() {
    extern __shared__ __align__(16) char sm[];
    const int tid = threadIdx.x, l = tid & 31, wid = tid >> 5;
    const int ci = blockIdx.x, bh = blockIdx.y, h = bh & (NH - 1);
    const float lg = lg2gamma(h);
    const uint32_t sb = smaddr(sm);
    const size_t base = (size_t)bh * NT * HD + (size_t)ci * 128 * HD;

    {
        const int j = tid;
        const float w = exp2f(lg * (float)(127 - j));
        const bf16* Kh = g_Kh + base + (size_t)j * HD;
        const bf16* Kl = g_Kl + base + (size_t)j * HD;
        const bf16* Vh = g_Vh + base + (size_t)j * HD;
        const bf16* Vl = g_Vl + base + (size_t)j * HD;
#pragma unroll
        for (int seg = 0; seg < 8; seg++) {
            uint4 khv = *(const uint4*)(Kh + seg * 8);
            uint4 klv = *(const uint4*)(Kl + seg * 8);
            const bf162* kh2 = (const bf162*)&khv;
            const bf162* kl2 = (const bf162*)&klv;
            uint32_t oh[4], ol[4];
#pragma unroll
            for (int q = 0; q < 4; q++) {
                float f0 = __bfloat162float(kh2[q].x) + __bfloat162float(kl2[q].x);
                float f1 = __bfloat162float(kh2[q].y) + __bfloat162float(kl2[q].y);
                f0 *= w; f1 *= w;
                bf16 h0 = __float2bfloat16(f0), h1 = __float2bfloat16(f1);
                float r0 = f0 - __bfloat162float(h0);
                float r1 = f1 - __bfloat162float(h1);
                ol[q] = pk2(r0, r1);
                bf162 hv; hv.x = h0; hv.y = h1;
                oh[q] = *(uint32_t*)&hv;
            }
            *(uint4*)(sm + CWK(0) + (j * CST + seg * 8) * 2) = *(uint4*)oh;
            *(uint4*)(sm + CWK(1) + (j * CST + seg * 8) * 2) = *(uint4*)ol;
            *(uint4*)(sm + CV(0) + (j * CST + seg * 8) * 2) = *(const uint4*)(Vh + seg * 8);
            *(uint4*)(sm + CV(1) + (j * CST + seg * 8) * 2) = *(const uint4*)(Vl + seg * 8);
        }
    }
    __syncthreads();

    float acc[8][4];
#pragma unroll
    for (int ni = 0; ni < 8; ni++)
#pragma unroll
        for (int q = 0; q < 4; q++) acc[ni][q] = 0.f;

#pragma unroll
    for (int ks = 0; ks < 8; ks++) {
        uint32_t ah[4], al[4];
        {
            int row = ks * 16 + (l & 7) + ((l >> 4) & 1) * 8;
            int col = 16 * wid + ((l >> 3) & 1) * 8;
            ldsm4t(ah, sb + CWK(0) + (row * CST + col) * 2);
            ldsm4t(al, sb + CWK(1) + (row * CST + col) * 2);
        }
        uint32_t bv[2][8][2];
#pragma unroll
        for (int p = 0; p < 2; p++)
#pragma unroll
            for (int na = 0; na < 4; na++) {
                int row = ks * 16 + ((l >> 3) & 1) * 8 + (l & 7);
                int col = na * 16 + (l >> 4) * 8;
                uint32_t r4[4];
                ldsm4t(r4, sb + CV(p) + (row * CST + col) * 2);
                bv[p][na * 2][0] = r4[0]; bv[p][na * 2][1] = r4[1];
                bv[p][na * 2 + 1][0] = r4[2]; bv[p][na * 2 + 1][1] = r4[3];
            }
#pragma unroll
        for (int ni = 0; ni < 8; ni++) mma_bf(acc[ni], ah, bv[0][ni]);
#pragma unroll
        for (int ni = 0; ni < 8; ni++) mma_bf(acc[ni], ah, bv[1][ni]);
#pragma unroll
        for (int ni = 0; ni < 8; ni++) mma_bf(acc[ni], al, bv[0][ni]);
    }

    float* U = g_U + ((size_t)bh * NCHUNK + ci) * HD * HD;
    const int g = l >> 2, tq = l & 3;
#pragma unroll
    for (int ni = 0; ni < 8; ni++) {
        int col = ni * 8 + 2 * tq;
        int row1 = 16 * wid + g, row2 = row1 + 8;
        *(float2*)(U + row1 * HD + col) = make_float2(acc[ni][0], acc[ni][1]);
        *(float2*)(U + row2 * HD + col) = make_float2(acc[ni][2], acc[ni][3]);
    }
}

// ---------------------------------------------------------------------------
// Phase C: intra-chunk quadratic + fused fp32-U state scan + GN partial (fp32).
// ---------------------------------------------------------------------------
#define RST 72
#define RQ(p)  ((p)*18432)
#define RK(p)  (36864 + (p)*9216)
#define RV(p)  (55296 + (p)*9216)
#define RDW    73728
#define RET_SMEM 74752

__global__ __launch_bounds__(256, 2) void retention_chunk_kernel() {
    extern __shared__ __align__(16) char sm[];
    float* dw = (float*)(sm + RDW);
    const int tid = threadIdx.x, l = tid & 31, wid = tid >> 5;
    const int bh = blockIdx.y, h = bh & (NH - 1);
    const int ci = blockIdx.x;
    const int t0 = ci * 128;
    const float lg = lg2gamma(h);
    const uint32_t sb = smaddr(sm);
    const size_t base = (size_t)bh * NT * HD;

#pragma unroll
    for (int p = 0; p < 2; p++) {
        const bf16* Qp = (p ? g_Ql : g_Qh) + base + (size_t)t0 * HD;
#pragma unroll
        for (int i = 0; i < 4; i++) {
            int flat = tid + 256 * i;
            int row = flat >> 3, seg = flat & 7;
            uint4 v = *(const uint4*)(Qp + (size_t)row * HD + seg * 8);
            *(uint4*)(sm + RQ(p) + (row * RST + seg * 8) * 2) = v;
        }
    }
    __syncthreads();

    const uint32_t aq_addr_base = sb + ((wid * 16 + (l & 7) + ((l >> 3) & 1) * 8) * RST
                                        + (l >> 4) * 8) * 2;

    float oacc[8][4];
#pragma unroll
    for (int ni = 0; ni < 8; ni++)
#pragma unroll
        for (int q = 0; q < 4; q++) oacc[ni][q] = 0.f;

    const int g = l >> 2, tq = l & 3;
    const int il = 16 * wid + g;

    for (int s0 = t0; s0 <= t0 + 64; s0 += 64) {
        __syncthreads();
#pragma unroll
        for (int p = 0; p < 2; p++) {
            const bf16* Kp = (p ? g_Kl : g_Kh) + base + (size_t)s0 * HD;
            const bf16* Vp = (p ? g_Vl : g_Vh) + base + (size_t)s0 * HD;
#pragma unroll
            for (int i = 0; i < 2; i++) {
                int flat = tid + 256 * i;
                int row = flat >> 3, seg = flat & 7;
                uint4 kv = *(const uint4*)(Kp + (size_t)row * HD + seg * 8);
                *(uint4*)(sm + RK(p) + (row * RST + seg * 8) * 2) = kv;
                uint4 vv = *(const uint4*)(Vp + (size_t)row * HD + seg * 8);
                *(uint4*)(sm + RV(p) + (row * RST + seg * 8) * 2) = vv;
            }
        }
        if (tid < 192) {
            int diff = t0 - s0 - 63 + tid;
            dw[tid] = (diff >= 0) ? 0.125f * exp2f(lg * (float)diff) : 0.f;
        }
        __syncthreads();

        float sacc[8][4];
#pragma unroll
        for (int ni = 0; ni < 8; ni++)
#pragma unroll
            for (int q = 0; q < 4; q++) sacc[ni][q] = 0.f;
#pragma unroll
        for (int kc = 0; kc < 4; kc++) {
            uint32_t aq0[4], aq1[4];
            ldsm4(aq0, aq_addr_base + RQ(0) + kc * 32);
            ldsm4(aq1, aq_addr_base + RQ(1) + kc * 32);
            uint32_t bk[2][8][2];
#pragma unroll
            for (int p = 0; p < 2; p++)
#pragma unroll
                for (int na = 0; na < 4; na++) {
                    int row = na * 16 + (l >> 4) * 8 + (l & 7);
                    int col = kc * 16 + ((l >> 3) & 1) * 8;
                    uint32_t r4[4];
                    ldsm4(r4, sb + RK(p) + (row * RST + col) * 2);
                    bk[p][na * 2][0] = r4[0]; bk[p][na * 2][1] = r4[1];
                    bk[p][na * 2 + 1][0] = r4[2]; bk[p][na * 2 + 1][1] = r4[3];
                }
#pragma unroll
            for (int ni = 0; ni < 8; ni++) mma_bf(sacc[ni], aq0, bk[0][ni]);
#pragma unroll
            for (int ni = 0; ni < 8; ni++) mma_bf(sacc[ni], aq0, bk[1][ni]);
#pragma unroll
            for (int ni = 0; ni < 8; ni++) mma_bf(sacc[ni], aq1, bk[0][ni]);
        }

#pragma unroll
        for (int ni = 0; ni < 8; ni++) {
            int jb = ni * 8 + 2 * tq;
            sacc[ni][0] *= dw[63 + il - jb];
            sacc[ni][1] *= dw[63 + il - (jb + 1)];
            sacc[ni][2] *= dw[63 + il + 8 - jb];
            sacc[ni][3] *= dw[63 + il + 8 - (jb + 1)];
        }

        uint32_t ash[4][4], asl[4][4];
#pragma unroll
        for (int kc = 0; kc < 4; kc++) {
            const float* e0 = sacc[2 * kc];
            const float* e1 = sacc[2 * kc + 1];
            float src[8] = {e0[0], e0[1], e0[2], e0[3], e1[0], e1[1], e1[2], e1[3]};
            float hv[8], lv[8];
#pragma unroll
            for (int q = 0; q < 8; q++) {
                bf16 hb = __float2bfloat16(src[q]);
                hv[q] = __bfloat162float(hb);
                lv[q] = src[q] - hv[q];
            }
            ash[kc][0] = pk2(hv[0], hv[1]); ash[kc][1] = pk2(hv[2], hv[3]);
            ash[kc][2] = pk2(hv[4], hv[5]); ash[kc][3] = pk2(hv[6], hv[7]);
            asl[kc][0] = pk2(lv[0], lv[1]); asl[kc][1] = pk2(lv[2], lv[3]);
            asl[kc][2] = pk2(lv[4], lv[5]); asl[kc][3] = pk2(lv[6], lv[7]);
        }

#pragma unroll
        for (int kc = 0; kc < 4; kc++) {
            uint32_t bv[2][8][2];
#pragma unroll
            for (int p = 0; p < 2; p++)
#pragma unroll
                for (int na = 0; na < 4; na++) {
                    int row = kc * 16 + ((l >> 3) & 1) * 8 + (l & 7);
                    int col = na * 16 + (l >> 4) * 8;
                    uint32_t r4[4];
                    ldsm4t(r4, sb + RV(p) + (row * RST + col) * 2);
                    bv[p][na * 2][0] = r4[0]; bv[p][na * 2][1] = r4[1];
                    bv[p][na * 2 + 1][0] = r4[2]; bv[p][na * 2 + 1][1] = r4[3];
                }
#pragma unroll
            for (int ni = 0; ni < 8; ni++) mma_bf(oacc[ni], ash[kc], bv[0][ni]);
#pragma unroll
            for (int ni = 0; ni < 8; ni++) mma_bf(oacc[ni], ash[kc], bv[1][ni]);
#pragma unroll
            for (int ni = 0; ni < 8; ni++) mma_bf(oacc[ni], asl[kc], bv[0][ni]);
        }
    }

    // fused fp32-U state scan: state = sum_{c<ci} g128^(ci-1-c) * U_c
    __syncthreads();
    {
        const float g128 = exp2f(lg * 128.0f);
        const int row = tid >> 2;
        const int c0 = (tid & 3) * 16;
        float st[16];
#pragma unroll
        for (int j = 0; j < 16; j++) st[j] = 0.f;
        for (int c = 0; c < ci; c++) {
            const float* U = g_U + ((size_t)bh * NCHUNK + c) * HD * HD + row * HD + c0;
#pragma unroll
            for (int j = 0; j < 16; j++) st[j] = st[j] * g128 + U[j];
        }
#pragma unroll
        for (int j = 0; j < 16; j += 2) {
            bf16 h0 = __float2bfloat16(st[j]), h1 = __float2bfloat16(st[j + 1]);
            float l0 = st[j] - __bfloat162float(h0);
            float l1 = st[j + 1] - __bfloat162float(h1);
            bf162 hv; hv.x = h0; hv.y = h1;
            *(bf162*)(sm + RK(0) + (row * RST + c0 + j) * 2) = hv;
            bf162 lv; lv.x = __float2bfloat16(l0); lv.y = __float2bfloat16(l1);
            *(bf162*)(sm + RK(1) + (row * RST + c0 + j) * 2) = lv;
        }
    }
    __syncthreads();

    float cacc[8][4];
#pragma unroll
    for (int ni = 0; ni < 8; ni++)
#pragma unroll
        for (int q = 0; q < 4; q++) cacc[ni][q] = 0.f;
#pragma unroll
    for (int kc = 0; kc < 4; kc++) {
        uint32_t aq0[4], aq1[4];
        ldsm4(aq0, aq_addr_base + RQ(0) + kc * 32);
        ldsm4(aq1, aq_addr_base + RQ(1) + kc * 32);
        uint32_t bs[2][8][2];
#pragma unroll
        for (int p = 0; p < 2; p++)
#pragma unroll
            for (int na = 0; na < 4; na++) {
                int row = kc * 16 + ((l >> 3) & 1) * 8 + (l & 7);
                int col = na * 16 + (l >> 4) * 8;
                uint32_t r4[4];
                ldsm4t(r4, sb + RK(p) + (row * RST + col) * 2);
                bs[p][na * 2][0] = r4[0]; bs[p][na * 2][1] = r4[1];
                bs[p][na * 2 + 1][0] = r4[2]; bs[p][na * 2 + 1][1] = r4[3];
            }
#pragma unroll
        for (int ni = 0; ni < 8; ni++) mma_bf(cacc[ni], aq0, bs[0][ni]);
#pragma unroll
        for (int ni = 0; ni < 8; ni++) mma_bf(cacc[ni], aq0, bs[1][ni]);
#pragma unroll
        for (int ni = 0; ni < 8; ni++) mma_bf(cacc[ni], aq1, bs[0][ni]);
    }
    {
        const float w1 = 0.125f * exp2f(lg * (float)(il + 1));
        const float w2 = 0.125f * exp2f(lg * (float)(il + 9));
#pragma unroll
        for (int ni = 0; ni < 8; ni++) {
            oacc[ni][0] += w1 * cacc[ni][0];
            oacc[ni][1] += w1 * cacc[ni][1];
            oacc[ni][2] += w2 * cacc[ni][2];
            oacc[ni][3] += w2 * cacc[ni][3];
        }
    }

    // write O (fp32)
#pragma unroll
    for (int ni = 0; ni < 8; ni++) {
        int col = ni * 8 + 2 * tq;
        int r1 = t0 + il, r2 = r1 + 8;
        *(float2*)(g_O + (base + (size_t)r1 * HD + col)) = make_float2(oacc[ni][0], oacc[ni][1]);
        *(float2*)(g_O + (base + (size_t)r2 * HD + col)) = make_float2(oacc[ni][2], oacc[ni][3]);
    }

    // GroupNorm partial in fp32 (warp butterfly; doubles only for 8 partials)
    {
        float s1 = 0.f, s2 = 0.f;
#pragma unroll
        for (int ni = 0; ni < 8; ni++)
#pragma unroll
            for (int q = 0; q < 4; q++) {
                float v = oacc[ni][q];
                s1 += v;
                s2 += v * v;
            }
#pragma unroll
        for (int o = 16; o > 0; o >>= 1) {
            s1 += __shfl_xor_sync(0xFFFFFFFFu, s1, o);
            s2 += __shfl_xor_sync(0xFFFFFFFFu, s2, o);
        }
        float* w1p = (float*)(sm + RV(0));
        float* w2p = (float*)(sm + RV(0) + 64);
        if (l == 0) { w1p[wid] = s1; w2p[wid] = s2; }
        __syncthreads();
        if (tid == 0) {
            double a = 0.0, b2 = 0.0;
#pragma unroll
            for (int w = 0; w < 8; w++) { a += (double)w1p[w]; b2 += (double)w2p[w]; }
            g_gnp[bh * NCHUNK + ci] = make_double2(a, b2);
        }
    }
}

// ---------------------------------------------------------------------------
// GroupNorm apply -> fp16 split Yn
// ---------------------------------------------------------------------------
__global__ __launch_bounds__(256) void gn_apply_kernel(const float* __restrict__ gnw,
                                                       const float* __restrict__ gnb) {
    const int part = blockIdx.x, bh = blockIdx.y;
    const int b = bh >> 4, h = bh & 15;
    double s1 = 0.0, s2 = 0.0;
#pragma unroll
    for (int p = 0; p < NCHUNK; p++) {
        double2 v = g_gnp[bh * NCHUNK + p];
        s1 += v.x; s2 += v.y;
    }
    const double n = (double)(NT * HD);
    double mud = s1 / n;
    double var = s2 / n - mud * mud;
    const float mu = (float)mud;
    const float rs = (float)(1.0 / sqrt(var + 1e-5));

    const float* bsrc = g_O + (size_t)bh * NT * HD;
    const int tid = threadIdx.x;
#pragma unroll 8
    for (int k = 0; k < 64; k++) {
        int i = part * 16384 + tid + 256 * k;
        int t = i >> 6, d = i & 63;
        int c = h * 64 + d;
        float v = (bsrc[i] - mu) * rs * gnw[c] + gnb[c];
        size_t idx = ((size_t)b * NT + t) * NC + c;
        __half hv = __float2half_rn(v);
        g_Ynh[idx] = hv;
        g_Ynl[idx] = __float2half_rn(v - __half2float(hv));
    }
}

// ---------------------------------------------------------------------------
// Launch. Launch #4 = retention_chunk (profiled slot).
// ---------------------------------------------------------------------------
extern "C" void kernel_launch(void* const* d_in, const int* in_sizes, int n_in,
                              void* d_out, int out_size) {
    const float* x   = (const float*)d_in[0];
    const float* Wq  = (const float*)d_in[1];
    const float* Wk  = (const float*)d_in[2];
    const float* Wv  = (const float*)d_in[3];
    const float* Wo  = (const float*)d_in[4];
    const float* gnw = (const float*)d_in[5];
    const float* gnb = (const float*)d_in[6];
    float* out = (float*)d_out;

    cudaFuncSetAttribute(gemm_mma<0>, cudaFuncAttributeMaxDynamicSharedMemorySize, GEMM_SMEM);
    cudaFuncSetAttribute(gemm_mma<1>, cudaFuncAttributeMaxDynamicSharedMemorySize, GEMM_SMEM);
    cudaFuncSetAttribute(chunk_state_kernel, cudaFuncAttributeMaxDynamicSharedMemorySize, CHUNK_SMEM);
    cudaFuncSetAttribute(retention_chunk_kernel, cudaFuncAttributeMaxDynamicSharedMemorySize, RET_SMEM);

    split_all_kernel<<<(NX4 + 4 * NW4) / 256, 256>>>(
        (const float4*)x, (const float4*)Wq, (const float4*)Wk,
        (const float4*)Wv, (const float4*)Wo);                                 // 1
    gemm_mma<0><<<dim3(MTOT / 128, NC / 128, 3), 256, GEMM_SMEM>>>(nullptr);   // 2
    chunk_state_kernel<<<dim3(NCHUNK, NB * NH), 128, CHUNK_SMEM>>>();          // 3
    retention_chunk_kernel<<<dim3(NCHUNK, NB * NH), 256, RET_SMEM>>>();        // 4 (profiled)
    gn_apply_kernel<<<dim3(8, NB * NH), 256>>>(gnw, gnb);                      // 5
    gemm_mma<1><<<dim3(MTOT / 128, NC / 128, 1), 256, GEMM_SMEM>>>(out);       // 6
}

// round 15
// speedup vs baseline: 1.4211x; 1.0696x over previous
#include <cuda_runtime.h>
#include <cuda_bf16.h>
#include <cuda_fp16.h>
#include <math.h>
#include <cstdint>

#define NB 2
#define NT 2048
#define NH 16
#define HD 64
#define NC 1024
#define MTOT (NB*NT)   // 4096
#define NCHUNK 16      // T / 128

typedef __nv_bfloat16  bf16;
typedef __nv_bfloat162 bf162;

// ---------------------------------------------------------------------------
// Scratch (allocation-free rule: __device__ globals)
// ---------------------------------------------------------------------------
__device__ __align__(16) __half g_Xh[MTOT*NC], g_Xl[MTOT*NC];   // x split (fp16)
__device__ __align__(16) __half g_W16[4*NC*NC];                  // weights (fp16)
__device__ __align__(16) bf16 g_Qh[NB*NH*NT*HD], g_Ql[NB*NH*NT*HD];
__device__ __align__(16) bf16 g_Kh[NB*NH*NT*HD], g_Kl[NB*NH*NT*HD];
__device__ __align__(16) bf16 g_Vh[NB*NH*NT*HD], g_Vl[NB*NH*NT*HD];
__device__ __align__(16) float g_O[NB*NH*NT*HD];
__device__ __align__(16) __half g_Ynh[MTOT*NC], g_Ynl[MTOT*NC];
__device__ __align__(16) float g_U[NB*NH*NCHUNK*HD*HD];
__device__ double2 g_gnp[NB*NH*NCHUNK];

// ---------------------------------------------------------------------------
// Helpers
// ---------------------------------------------------------------------------
__device__ __forceinline__ uint32_t smaddr(const void* p) {
    uint32_t a;
    asm("{ .reg .u64 t; cvta.to.shared.u64 t, %1; cvt.u32.u64 %0, t; }"
        : "=r"(a) : "l"(p));
    return a;
}
__device__ __forceinline__ void ldsm4(uint32_t r[4], uint32_t a) {
    asm volatile("ldmatrix.sync.aligned.m8n8.x4.shared.b16 {%0,%1,%2,%3}, [%4];"
        : "=r"(r[0]), "=r"(r[1]), "=r"(r[2]), "=r"(r[3]) : "r"(a));
}
__device__ __forceinline__ void ldsm4t(uint32_t r[4], uint32_t a) {
    asm volatile("ldmatrix.sync.aligned.m8n8.x4.trans.shared.b16 {%0,%1,%2,%3}, [%4];"
        : "=r"(r[0]), "=r"(r[1]), "=r"(r[2]), "=r"(r[3]) : "r"(a));
}
__device__ __forceinline__ void mma_bf(float c[4], const uint32_t a[4], const uint32_t b[2]) {
    asm volatile(
        "mma.sync.aligned.m16n8k16.row.col.f32.bf16.bf16.f32 "
        "{%0,%1,%2,%3}, {%4,%5,%6,%7}, {%8,%9}, {%0,%1,%2,%3};"
        : "+f"(c[0]), "+f"(c[1]), "+f"(c[2]), "+f"(c[3])
        : "r"(a[0]), "r"(a[1]), "r"(a[2]), "r"(a[3]), "r"(b[0]), "r"(b[1]));
}
__device__ __forceinline__ void mma_f16(float c[4], const uint32_t a[4], const uint32_t b[2]) {
    asm volatile(
        "mma.sync.aligned.m16n8k16.row.col.f32.f16.f16.f32 "
        "{%0,%1,%2,%3}, {%4,%5,%6,%7}, {%8,%9}, {%0,%1,%2,%3};"
        : "+f"(c[0]), "+f"(c[1]), "+f"(c[2]), "+f"(c[3])
        : "r"(a[0]), "r"(a[1]), "r"(a[2]), "r"(a[3]), "r"(b[0]), "r"(b[1]));
}
__device__ __forceinline__ uint32_t pk2(float a, float b) {
    bf162 t = __floats2bfloat162_rn(a, b);
    return *reinterpret_cast<uint32_t*>(&t);
}
__device__ __forceinline__ float lg2gamma(int h) {
    double gamma = 1.0 - exp2(-5.0 - 0.5 * (double)h);
    return (float)log2(gamma);
}
__device__ __forceinline__ void cpa16(uint32_t s, const void* g) {
    asm volatile("cp.async.cg.shared.global [%0], [%1], 16;" :: "r"(s), "l"(g));
}
#define CP_COMMIT() asm volatile("cp.async.commit_group;" ::: "memory")
#define CP_WAIT0()  asm volatile("cp.async.wait_group 0;" ::: "memory")

__device__ __forceinline__ void split4h(float4 v, uint2& hi, uint2& lo) {
    __half2 h0 = __floats2half2_rn(v.x, v.y);
    __half2 h1 = __floats2half2_rn(v.z, v.w);
    float2 f0 = __half22float2(h0), f1 = __half22float2(h1);
    __half2 l0 = __floats2half2_rn(v.x - f0.x, v.y - f0.y);
    __half2 l1 = __floats2half2_rn(v.z - f1.x, v.w - f1.y);
    hi.x = *(uint32_t*)&h0; hi.y = *(uint32_t*)&h1;
    lo.x = *(uint32_t*)&l0; lo.y = *(uint32_t*)&l1;
}

// ---------------------------------------------------------------------------
// Fused split: x -> fp16 hi/lo; W -> fp16 single.
// ---------------------------------------------------------------------------
#define NX4 (MTOT*NC/4)
#define NW4 (NC*NC/4)

__global__ __launch_bounds__(256) void split_all_kernel(
    const float4* __restrict__ x,  const float4* __restrict__ wq,
    const float4* __restrict__ wk, const float4* __restrict__ wv,
    const float4* __restrict__ wo)
{
    int i = blockIdx.x * 256 + threadIdx.x;
    if (i < NX4) {
        uint2 hi, lo;
        split4h(x[i], hi, lo);
        *(uint2*)(g_Xh + 4 * (size_t)i) = hi;
        *(uint2*)(g_Xl + 4 * (size_t)i) = lo;
    } else {
        int j = i - NX4;
        int widx = j >> 18;
        int e = j & (NW4 - 1);
        const float4* w = (widx == 0) ? wq : (widx == 1) ? wk : (widx == 2) ? wv : wo;
        float4 v = w[e];
        __half2 a = __floats2half2_rn(v.x, v.y);
        __half2 b = __floats2half2_rn(v.z, v.w);
        uint2 o; o.x = *(uint32_t*)&a; o.y = *(uint32_t*)&b;
        *(uint2*)(g_W16 + (size_t)widx * NC * NC + 4 * (size_t)e) = o;
    }
}

// ---------------------------------------------------------------------------
// fp16 2-term GEMM, k-chunk 64 (16 barrier iterations instead of 32).
// BM=128, BN=128, warp tile 32x64, 8 warps, 2 CTAs/SM, cp.async 2-stage.
// ---------------------------------------------------------------------------
#define AST 72            // smem row stride (elements) for 64-col chunk
#define KCH 16            // 1024 / 64
#define APART 18432       // 128*72*2 bytes
#define BUFB  55296       // 2 A parts + 1 B
#define SOA(buf,p) ((buf)*BUFB + (p)*APART)
#define SOB(buf)   ((buf)*BUFB + 2*APART)
#define GEMM_SMEM (2*BUFB)   // 110592

template<int MODE>
__global__ __launch_bounds__(256, 2) void gemm_mma(float* __restrict__ Cf) {
    extern __shared__ __align__(16) char sm[];
    const int tid = threadIdx.x, l = tid & 31, wid = tid >> 5;
    const int wm = wid & 3, wn = wid >> 2;
    const int r0 = blockIdx.x * 128, n0 = blockIdx.y * 128;
    const int z = blockIdx.z;
    const int wsel = (MODE == 0) ? z : 3;

    const __half* Ah = (MODE == 0) ? g_Xh : g_Ynh;
    const __half* Al = (MODE == 0) ? g_Xl : g_Ynl;
    const __half* W  = g_W16 + (size_t)wsel * NC * NC;
    const uint32_t sb = smaddr(sm);

    float acc[2][8][4];
#pragma unroll
    for (int mi = 0; mi < 2; mi++)
#pragma unroll
        for (int ni = 0; ni < 8; ni++)
#pragma unroll
            for (int q = 0; q < 4; q++) acc[mi][ni][q] = 0.f;

    // one chunk = A 2048 x16B (2 parts) + B 1024 x16B = 3072 -> 12 per thread
    auto load_chunk = [&](int kb, int buf) {
#pragma unroll
        for (int i = 0; i < 12; i++) {
            int j = tid + 256 * i;
            if (j < 2048) {
                int part = j >> 10, row = (j >> 3) & 127, seg = j & 7;
                const __half* src = (part ? Al : Ah) + (size_t)(r0 + row) * NC + kb + seg * 8;
                cpa16(sb + SOA(buf, part) + (row * AST + seg * 8) * 2, src);
            } else {
                int jj = j - 2048;
                int row = (jj >> 3) & 127, seg = jj & 7;
                const __half* src = W + (size_t)(n0 + row) * NC + kb + seg * 8;
                cpa16(sb + SOB(buf) + (row * AST + seg * 8) * 2, src);
            }
        }
    };

    load_chunk(0, 0);
    CP_COMMIT();

    for (int c = 0; c < KCH; c++) {
        const int buf = c & 1;
        CP_WAIT0();
        __syncthreads();
        if (c + 1 < KCH) {
            load_chunk((c + 1) * 64, buf ^ 1);
            CP_COMMIT();
        }
#pragma unroll
        for (int ks = 0; ks < 64; ks += 16) {
            uint32_t af[2][2][4];
#pragma unroll
            for (int p = 0; p < 2; p++)
#pragma unroll
                for (int mi = 0; mi < 2; mi++) {
                    int row = wm * 32 + mi * 16 + (l & 7) + ((l >> 3) & 1) * 8;
                    int col = ks + (l >> 4) * 8;
                    ldsm4(af[p][mi], sb + SOA(buf, p) + (row * AST + col) * 2);
                }
            uint32_t bfr[8][2];
#pragma unroll
            for (int na = 0; na < 4; na++) {
                int row = wn * 64 + na * 16 + (l >> 4) * 8 + (l & 7);
                int col = ks + ((l >> 3) & 1) * 8;
                uint32_t r4[4];
                ldsm4(r4, sb + SOB(buf) + (row * AST + col) * 2);
                bfr[na * 2][0] = r4[0]; bfr[na * 2][1] = r4[1];
                bfr[na * 2 + 1][0] = r4[2]; bfr[na * 2 + 1][1] = r4[3];
            }
#pragma unroll
            for (int mi = 0; mi < 2; mi++)
#pragma unroll
                for (int ni = 0; ni < 8; ni++) mma_f16(acc[mi][ni], af[0][mi], bfr[ni]);
#pragma unroll
            for (int mi = 0; mi < 2; mi++)
#pragma unroll
                for (int ni = 0; ni < 8; ni++) mma_f16(acc[mi][ni], af[1][mi], bfr[ni]);
        }
    }

    const int g = l >> 2, tq = l & 3;
    bf16* oh = nullptr; bf16* ol = nullptr;
    if (MODE == 0) {
        oh = (z == 0) ? g_Qh : (z == 1) ? g_Kh : g_Vh;
        ol = (z == 0) ? g_Ql : (z == 1) ? g_Kl : g_Vl;
    }
#pragma unroll
    for (int mi = 0; mi < 2; mi++)
#pragma unroll
        for (int ni = 0; ni < 8; ni++) {
            int rbase = r0 + wm * 32 + mi * 16 + g;
            int n = n0 + wn * 64 + ni * 8 + 2 * tq;
#pragma unroll
            for (int rr = 0; rr < 2; rr++) {
                int row = rbase + rr * 8;
                float v0 = acc[mi][ni][rr * 2 + 0];
                float v1 = acc[mi][ni][rr * 2 + 1];
                if (MODE == 0) {
                    int b = row >> 11, t = row & (NT - 1);
                    int hh = n >> 6, d = n & 63;
                    size_t idx = (((size_t)b * NH + hh) * NT + t) * HD + d;
                    bf16 h0 = __float2bfloat16(v0);
                    bf16 h1 = __float2bfloat16(v1);
                    bf162 hv; hv.x = h0; hv.y = h1;
                    bf162 lv;
                    lv.x = __float2bfloat16(v0 - __bfloat162float(h0));
                    lv.y = __float2bfloat16(v1 - __bfloat162float(h1));
                    *(bf162*)(oh + idx) = hv;
                    *(bf162*)(ol + idx) = lv;
                } else {
                    *(float2*)(Cf + (size_t)row * NC + n) = make_float2(v0, v1);
                }
            }
        }
}

// ---------------------------------------------------------------------------
// Phase A: per-chunk KV summary -> fp32 U (bf16x3, unchanged)
// ---------------------------------------------------------------------------
#define CST 72
#define CWK(p) ((p)*18432)
#define CV(p)  (36864 + (p)*18432)
#define CHUNK_SMEM 73728

__global__ __launch_bounds__(128) void chunk_state_kernel() {
    extern __shared__ __align__(16) char sm[];
    const int tid = threadIdx.x, l = tid & 31, wid = tid >> 5;
    const int ci = blockIdx.x, bh = blockIdx.y, h = bh & (NH - 1);
    const float lg = lg2gamma(h);
    const uint32_t sb = smaddr(sm);
    const size_t base = (size_t)bh * NT * HD + (size_t)ci * 128 * HD;

    {
        const int j = tid;
        const float w = exp2f(lg * (float)(127 - j));
        const bf16* Kh = g_Kh + base + (size_t)j * HD;
        const bf16* Kl = g_Kl + base + (size_t)j * HD;
        const bf16* Vh = g_Vh + base + (size_t)j * HD;
        const bf16* Vl = g_Vl + base + (size_t)j * HD;
#pragma unroll
        for (int seg = 0; seg < 8; seg++) {
            uint4 khv = *(const uint4*)(Kh + seg * 8);
            uint4 klv = *(const uint4*)(Kl + seg * 8);
            const bf162* kh2 = (const bf162*)&khv;
            const bf162* kl2 = (const bf162*)&klv;
            uint32_t oh[4], ol[4];
#pragma unroll
            for (int q = 0; q < 4; q++) {
                float f0 = __bfloat162float(kh2[q].x) + __bfloat162float(kl2[q].x);
                float f1 = __bfloat162float(kh2[q].y) + __bfloat162float(kl2[q].y);
                f0 *= w; f1 *= w;
                bf16 h0 = __float2bfloat16(f0), h1 = __float2bfloat16(f1);
                float r0 = f0 - __bfloat162float(h0);
                float r1 = f1 - __bfloat162float(h1);
                ol[q] = pk2(r0, r1);
                bf162 hv; hv.x = h0; hv.y = h1;
                oh[q] = *(uint32_t*)&hv;
            }
            *(uint4*)(sm + CWK(0) + (j * CST + seg * 8) * 2) = *(uint4*)oh;
            *(uint4*)(sm + CWK(1) + (j * CST + seg * 8) * 2) = *(uint4*)ol;
            *(uint4*)(sm + CV(0) + (j * CST + seg * 8) * 2) = *(const uint4*)(Vh + seg * 8);
            *(uint4*)(sm + CV(1) + (j * CST + seg * 8) * 2) = *(const uint4*)(Vl + seg * 8);
        }
    }
    __syncthreads();

    float acc[8][4];
#pragma unroll
    for (int ni = 0; ni < 8; ni++)
#pragma unroll
        for (int q = 0; q < 4; q++) acc[ni][q] = 0.f;

#pragma unroll
    for (int ks = 0; ks < 8; ks++) {
        uint32_t ah[4], al[4];
        {
            int row = ks * 16 + (l & 7) + ((l >> 4) & 1) * 8;
            int col = 16 * wid + ((l >> 3) & 1) * 8;
            ldsm4t(ah, sb + CWK(0) + (row * CST + col) * 2);
            ldsm4t(al, sb + CWK(1) + (row * CST + col) * 2);
        }
        uint32_t bv[2][8][2];
#pragma unroll
        for (int p = 0; p < 2; p++)
#pragma unroll
            for (int na = 0; na < 4; na++) {
                int row = ks * 16 + ((l >> 3) & 1) * 8 + (l & 7);
                int col = na * 16 + (l >> 4) * 8;
                uint32_t r4[4];
                ldsm4t(r4, sb + CV(p) + (row * CST + col) * 2);
                bv[p][na * 2][0] = r4[0]; bv[p][na * 2][1] = r4[1];
                bv[p][na * 2 + 1][0] = r4[2]; bv[p][na * 2 + 1][1] = r4[3];
            }
#pragma unroll
        for (int ni = 0; ni < 8; ni++) mma_bf(acc[ni], ah, bv[0][ni]);
#pragma unroll
        for (int ni = 0; ni < 8; ni++) mma_bf(acc[ni], ah, bv[1][ni]);
#pragma unroll
        for (int ni = 0; ni < 8; ni++) mma_bf(acc[ni], al, bv[0][ni]);
    }

    float* U = g_U + ((size_t)bh * NCHUNK + ci) * HD * HD;
    const int g = l >> 2, tq = l & 3;
#pragma unroll
    for (int ni = 0; ni < 8; ni++) {
        int col = ni * 8 + 2 * tq;
        int row1 = 16 * wid + g, row2 = row1 + 8;
        *(float2*)(U + row1 * HD + col) = make_float2(acc[ni][0], acc[ni][1]);
        *(float2*)(U + row2 * HD + col) = make_float2(acc[ni][2], acc[ni][3]);
    }
}

// ---------------------------------------------------------------------------
// Phase C: intra-chunk quadratic + fused fp32-U scan + GN partial (fp32).
// ---------------------------------------------------------------------------
#define RST 72
#define RQ(p)  ((p)*18432)
#define RK(p)  (36864 + (p)*9216)
#define RV(p)  (55296 + (p)*9216)
#define RDW    73728
#define RET_SMEM 74752

__global__ __launch_bounds__(256, 2) void retention_chunk_kernel() {
    extern __shared__ __align__(16) char sm[];
    float* dw = (float*)(sm + RDW);
    const int tid = threadIdx.x, l = tid & 31, wid = tid >> 5;
    const int bh = blockIdx.y, h = bh & (NH - 1);
    const int ci = blockIdx.x;
    const int t0 = ci * 128;
    const float lg = lg2gamma(h);
    const uint32_t sb = smaddr(sm);
    const size_t base = (size_t)bh * NT * HD;

#pragma unroll
    for (int p = 0; p < 2; p++) {
        const bf16* Qp = (p ? g_Ql : g_Qh) + base + (size_t)t0 * HD;
#pragma unroll
        for (int i = 0; i < 4; i++) {
            int flat = tid + 256 * i;
            int row = flat >> 3, seg = flat & 7;
            uint4 v = *(const uint4*)(Qp + (size_t)row * HD + seg * 8);
            *(uint4*)(sm + RQ(p) + (row * RST + seg * 8) * 2) = v;
        }
    }
    __syncthreads();

    const uint32_t aq_addr_base = sb + ((wid * 16 + (l & 7) + ((l >> 3) & 1) * 8) * RST
                                        + (l >> 4) * 8) * 2;

    float oacc[8][4];
#pragma unroll
    for (int ni = 0; ni < 8; ni++)
#pragma unroll
        for (int q = 0; q < 4; q++) oacc[ni][q] = 0.f;

    const int g = l >> 2, tq = l & 3;
    const int il = 16 * wid + g;

    for (int s0 = t0; s0 <= t0 + 64; s0 += 64) {
        __syncthreads();
#pragma unroll
        for (int p = 0; p < 2; p++) {
            const bf16* Kp = (p ? g_Kl : g_Kh) + base + (size_t)s0 * HD;
            const bf16* Vp = (p ? g_Vl : g_Vh) + base + (size_t)s0 * HD;
#pragma unroll
            for (int i = 0; i < 2; i++) {
                int flat = tid + 256 * i;
                int row = flat >> 3, seg = flat & 7;
                uint4 kv = *(const uint4*)(Kp + (size_t)row * HD + seg * 8);
                *(uint4*)(sm + RK(p) + (row * RST + seg * 8) * 2) = kv;
                uint4 vv = *(const uint4*)(Vp + (size_t)row * HD + seg * 8);
                *(uint4*)(sm + RV(p) + (row * RST + seg * 8) * 2) = vv;
            }
        }
        if (tid < 192) {
            int diff = t0 - s0 - 63 + tid;
            dw[tid] = (diff >= 0) ? 0.125f * exp2f(lg * (float)diff) : 0.f;
        }
        __syncthreads();

        float sacc[8][4];
#pragma unroll
        for (int ni = 0; ni < 8; ni++)
#pragma unroll
            for (int q = 0; q < 4; q++) sacc[ni][q] = 0.f;
#pragma unroll
        for (int kc = 0; kc < 4; kc++) {
            uint32_t aq0[4], aq1[4];
            ldsm4(aq0, aq_addr_base + RQ(0) + kc * 32);
            ldsm4(aq1, aq_addr_base + RQ(1) + kc * 32);
            uint32_t bk[2][8][2];
#pragma unroll
            for (int p = 0; p < 2; p++)
#pragma unroll
                for (int na = 0; na < 4; na++) {
                    int row = na * 16 + (l >> 4) * 8 + (l & 7);
                    int col = kc * 16 + ((l >> 3) & 1) * 8;
                    uint32_t r4[4];
                    ldsm4(r4, sb + RK(p) + (row * RST + col) * 2);
                    bk[p][na * 2][0] = r4[0]; bk[p][na * 2][1] = r4[1];
                    bk[p][na * 2 + 1][0] = r4[2]; bk[p][na * 2 + 1][1] = r4[3];
                }
#pragma unroll
            for (int ni = 0; ni < 8; ni++) mma_bf(sacc[ni], aq0, bk[0][ni]);
#pragma unroll
            for (int ni = 0; ni < 8; ni++) mma_bf(sacc[ni], aq0, bk[1][ni]);
#pragma unroll
            for (int ni = 0; ni < 8; ni++) mma_bf(sacc[ni], aq1, bk[0][ni]);
        }

#pragma unroll
        for (int ni = 0; ni < 8; ni++) {
            int jb = ni * 8 + 2 * tq;
            sacc[ni][0] *= dw[63 + il - jb];
            sacc[ni][1] *= dw[63 + il - (jb + 1)];
            sacc[ni][2] *= dw[63 + il + 8 - jb];
            sacc[ni][3] *= dw[63 + il + 8 - (jb + 1)];
        }

        uint32_t ash[4][4], asl[4][4];
#pragma unroll
        for (int kc = 0; kc < 4; kc++) {
            const float* e0 = sacc[2 * kc];
            const float* e1 = sacc[2 * kc + 1];
            float src[8] = {e0[0], e0[1], e0[2], e0[3], e1[0], e1[1], e1[2], e1[3]};
            float hv[8], lv[8];
#pragma unroll
            for (int q = 0; q < 8; q++) {
                bf16 hb = __float2bfloat16(src[q]);
                hv[q] = __bfloat162float(hb);
                lv[q] = src[q] - hv[q];
            }
            ash[kc][0] = pk2(hv[0], hv[1]); ash[kc][1] = pk2(hv[2], hv[3]);
            ash[kc][2] = pk2(hv[4], hv[5]); ash[kc][3] = pk2(hv[6], hv[7]);
            asl[kc][0] = pk2(lv[0], lv[1]); asl[kc][1] = pk2(lv[2], lv[3]);
            asl[kc][2] = pk2(lv[4], lv[5]); asl[kc][3] = pk2(lv[6], lv[7]);
        }

#pragma unroll
        for (int kc = 0; kc < 4; kc++) {
            uint32_t bv[2][8][2];
#pragma unroll
            for (int p = 0; p < 2; p++)
#pragma unroll
                for (int na = 0; na < 4; na++) {
                    int row = kc * 16 + ((l >> 3) & 1) * 8 + (l & 7);
                    int col = na * 16 + (l >> 4) * 8;
                    uint32_t r4[4];
                    ldsm4t(r4, sb + RV(p) + (row * RST + col) * 2);
                    bv[p][na * 2][0] = r4[0]; bv[p][na * 2][1] = r4[1];
                    bv[p][na * 2 + 1][0] = r4[2]; bv[p][na * 2 + 1][1] = r4[3];
                }
#pragma unroll
            for (int ni = 0; ni < 8; ni++) mma_bf(oacc[ni], ash[kc], bv[0][ni]);
#pragma unroll
            for (int ni = 0; ni < 8; ni++) mma_bf(oacc[ni], ash[kc], bv[1][ni]);
#pragma unroll
            for (int ni = 0; ni < 8; ni++) mma_bf(oacc[ni], asl[kc], bv[0][ni]);
        }
    }

    // fused fp32-U state scan
    __syncthreads();
    {
        const float g128 = exp2f(lg * 128.0f);
        const int row = tid >> 2;
        const int c0 = (tid & 3) * 16;
        float st[16];
#pragma unroll
        for (int j = 0; j < 16; j++) st[j] = 0.f;
        for (int c = 0; c < ci; c++) {
            const float* U = g_U + ((size_t)bh * NCHUNK + c) * HD * HD + row * HD + c0;
#pragma unroll
            for (int j = 0; j < 16; j++) st[j] = st[j] * g128 + U[j];
        }
#pragma unroll
        for (int j = 0; j < 16; j += 2) {
            bf16 h0 = __float2bfloat16(st[j]), h1 = __float2bfloat16(st[j + 1]);
            float l0 = st[j] - __bfloat162float(h0);
            float l1 = st[j + 1] - __bfloat162float(h1);
            bf162 hv; hv.x = h0; hv.y = h1;
            *(bf162*)(sm + RK(0) + (row * RST + c0 + j) * 2) = hv;
            bf162 lv; lv.x = __float2bfloat16(l0); lv.y = __float2bfloat16(l1);
            *(bf162*)(sm + RK(1) + (row * RST + c0 + j) * 2) = lv;
        }
    }
    __syncthreads();

    float cacc[8][4];
#pragma unroll
    for (int ni = 0; ni < 8; ni++)
#pragma unroll
        for (int q = 0; q < 4; q++) cacc[ni][q] = 0.f;
#pragma unroll
    for (int kc = 0; kc < 4; kc++) {
        uint32_t aq0[4], aq1[4];
        ldsm4(aq0, aq_addr_base + RQ(0) + kc * 32);
        ldsm4(aq1, aq_addr_base + RQ(1) + kc * 32);
        uint32_t bs[2][8][2];
#pragma unroll
        for (int p = 0; p < 2; p++)
#pragma unroll
            for (int na = 0; na < 4; na++) {
                int row = kc * 16 + ((l >> 3) & 1) * 8 + (l & 7);
                int col = na * 16 + (l >> 4) * 8;
                uint32_t r4[4];
                ldsm4t(r4, sb + RK(p) + (row * RST + col) * 2);
                bs[p][na * 2][0] = r4[0]; bs[p][na * 2][1] = r4[1];
                bs[p][na * 2 + 1][0] = r4[2]; bs[p][na * 2 + 1][1] = r4[3];
            }
#pragma unroll
        for (int ni = 0; ni < 8; ni++) mma_bf(cacc[ni], aq0, bs[0][ni]);
#pragma unroll
        for (int ni = 0; ni < 8; ni++) mma_bf(cacc[ni], aq0, bs[1][ni]);
#pragma unroll
        for (int ni = 0; ni < 8; ni++) mma_bf(cacc[ni], aq1, bs[0][ni]);
    }
    {
        const float w1 = 0.125f * exp2f(lg * (float)(il + 1));
        const float w2 = 0.125f * exp2f(lg * (float)(il + 9));
#pragma unroll
        for (int ni = 0; ni < 8; ni++) {
            oacc[ni][0] += w1 * cacc[ni][0];
            oacc[ni][1] += w1 * cacc[ni][1];
            oacc[ni][2] += w2 * cacc[ni][2];
            oacc[ni][3] += w2 * cacc[ni][3];
        }
    }

    // write O (fp32)
#pragma unroll
    for (int ni = 0; ni < 8; ni++) {
        int col = ni * 8 + 2 * tq;
        int r1 = t0 + il, r2 = r1 + 8;
        *(float2*)(g_O + (base + (size_t)r1 * HD + col)) = make_float2(oacc[ni][0], oacc[ni][1]);
        *(float2*)(g_O + (base + (size_t)r2 * HD + col)) = make_float2(oacc[ni][2], oacc[ni][3]);
    }

    // GroupNorm partial in fp32 (warp butterfly; doubles only for 8 partials)
    {
        float s1 = 0.f, s2 = 0.f;
#pragma unroll
        for (int ni = 0; ni < 8; ni++)
#pragma unroll
            for (int q = 0; q < 4; q++) {
                float v = oacc[ni][q];
                s1 += v;
                s2 += v * v;
            }
#pragma unroll
        for (int o = 16; o > 0; o >>= 1) {
            s1 += __shfl_xor_sync(0xFFFFFFFFu, s1, o);
            s2 += __shfl_xor_sync(0xFFFFFFFFu, s2, o);
        }
        float* w1p = (float*)(sm + RV(0));
        float* w2p = (float*)(sm + RV(0) + 64);
        if (l == 0) { w1p[wid] = s1; w2p[wid] = s2; }
        __syncthreads();
        if (tid == 0) {
            double a = 0.0, b2 = 0.0;
#pragma unroll
            for (int w = 0; w < 8; w++) { a += (double)w1p[w]; b2 += (double)w2p[w]; }
            g_gnp[bh * NCHUNK + ci] = make_double2(a, b2);
        }
    }
}

// ---------------------------------------------------------------------------
// GroupNorm apply -> fp16 split Yn
// ---------------------------------------------------------------------------
__global__ __launch_bounds__(256) void gn_apply_kernel(const float* __restrict__ gnw,
                                                       const float* __restrict__ gnb) {
    const int part = blockIdx.x, bh = blockIdx.y;
    const int b = bh >> 4, h = bh & 15;
    double s1 = 0.0, s2 = 0.0;
#pragma unroll
    for (int p = 0; p < NCHUNK; p++) {
        double2 v = g_gnp[bh * NCHUNK + p];
        s1 += v.x; s2 += v.y;
    }
    const double n = (double)(NT * HD);
    double mud = s1 / n;
    double var = s2 / n - mud * mud;
    const float mu = (float)mud;
    const float rs = (float)(1.0 / sqrt(var + 1e-5));

    const float* bsrc = g_O + (size_t)bh * NT * HD;
    const int tid = threadIdx.x;
#pragma unroll 8
    for (int k = 0; k < 64; k++) {
        int i = part * 16384 + tid + 256 * k;
        int t = i >> 6, d = i & 63;
        int c = h * 64 + d;
        float v = (bsrc[i] - mu) * rs * gnw[c] + gnb[c];
        size_t idx = ((size_t)b * NT + t) * NC + c;
        __half hv = __float2half_rn(v);
        g_Ynh[idx] = hv;
        g_Ynl[idx] = __float2half_rn(v - __half2float(hv));
    }
}

// ---------------------------------------------------------------------------
// Launch. Launch #4 = retention_chunk (profiled slot).
// ---------------------------------------------------------------------------
extern "C" void kernel_launch(void* const* d_in, const int* in_sizes, int n_in,
                              void* d_out, int out_size) {
    const float* x   = (const float*)d_in[0];
    const float* Wq  = (const float*)d_in[1];
    const float* Wk  = (const float*)d_in[2];
    const float* Wv  = (const float*)d_in[3];
    const float* Wo  = (const float*)d_in[4];
    const float* gnw = (const float*)d_in[5];
    const float* gnb = (const float*)d_in[6];
    float* out = (float*)d_out;

    cudaFuncSetAttribute(gemm_mma<0>, cudaFuncAttributeMaxDynamicSharedMemorySize, GEMM_SMEM);
    cudaFuncSetAttribute(gemm_mma<1>, cudaFuncAttributeMaxDynamicSharedMemorySize, GEMM_SMEM);
    cudaFuncSetAttribute(chunk_state_kernel, cudaFuncAttributeMaxDynamicSharedMemorySize, CHUNK_SMEM);
    cudaFuncSetAttribute(retention_chunk_kernel, cudaFuncAttributeMaxDynamicSharedMemorySize, RET_SMEM);

    split_all_kernel<<<(NX4 + 4 * NW4) / 256, 256>>>(
        (const float4*)x, (const float4*)Wq, (const float4*)Wk,
        (const float4*)Wv, (const float4*)Wo);                                 // 1
    gemm_mma<0><<<dim3(MTOT / 128, NC / 128, 3), 256, GEMM_SMEM>>>(nullptr);   // 2
    chunk_state_kernel<<<dim3(NCHUNK, NB * NH), 128, CHUNK_SMEM>>>();          // 3
    retention_chunk_kernel<<<dim3(NCHUNK, NB * NH), 256, RET_SMEM>>>();        // 4 (profiled)
    gn_apply_kernel<<<dim3(8, NB * NH), 256>>>(gnw, gnb);                      // 5
    gemm_mma<1><<<dim3(MTOT / 128, NC / 128, 1), 256, GEMM_SMEM>>>(out);       // 6
}